// round 1
// baseline (speedup 1.0000x reference)
#include <cuda_runtime.h>
#include <math.h>

// Problem dims (fixed by the dataset)
#define B_   2
#define T_   2048
#define C_   1024
#define H_   16
#define HD_  64
#define C3_  (3*C_)
#define M_   (B_*T_)          // 4096 rows

// ---------------- scratch (no cudaMalloc allowed) ----------------
__device__ float g_qkv[(size_t)M_ * C3_];   // [B*T, 3C]  ~50 MB
__device__ float g_y  [(size_t)M_ * C_];    // [B*T, C]   ~16 MB

// ---------------- tiled fp32 GEMM with bias: C = A[M,K] @ B[K,N] + bias ----------------
#define BM 128
#define BN 128
#define BK 16
#define TM 8
#define TN 8

__global__ __launch_bounds__(256, 2) void gemm_bias_kernel(
    const float* __restrict__ A, const float* __restrict__ Bw,
    const float* __restrict__ bias, float* __restrict__ Cout,
    int M, int N, int K)
{
    __shared__ float As[BK][BM];
    __shared__ float Bs[BK][BN];

    const int tid  = threadIdx.x;
    const int row0 = blockIdx.y * BM;
    const int col0 = blockIdx.x * BN;
    const int tx = tid & 15;   // 16 col-groups
    const int ty = tid >> 4;   // 16 row-groups

    float acc[TM][TN];
#pragma unroll
    for (int i = 0; i < TM; i++)
#pragma unroll
        for (int j = 0; j < TN; j++) acc[i][j] = 0.f;

    for (int k0 = 0; k0 < K; k0 += BK) {
        // A tile: 128 rows x 16 cols, stored transposed As[k][m]
#pragma unroll
        for (int it = 0; it < 2; it++) {
            int idx = tid + it * 256;         // 0..511
            int r   = idx >> 2;               // 0..127
            int c4  = (idx & 3) * 4;          // 0,4,8,12
            float4 v = *(const float4*)(A + (size_t)(row0 + r) * K + k0 + c4);
            As[c4 + 0][r] = v.x;
            As[c4 + 1][r] = v.y;
            As[c4 + 2][r] = v.z;
            As[c4 + 3][r] = v.w;
        }
        // B tile: 16 rows x 128 cols
#pragma unroll
        for (int it = 0; it < 2; it++) {
            int idx = tid + it * 256;         // 0..511
            int r   = idx >> 5;               // 0..15
            int c4  = (idx & 31) * 4;         // 0..124
            *(float4*)&Bs[r][c4] =
                *(const float4*)(Bw + (size_t)(k0 + r) * N + col0 + c4);
        }
        __syncthreads();

#pragma unroll
        for (int kk = 0; kk < BK; kk++) {
            float a[TM], b[TN];
            *(float4*)&a[0] = *(float4*)&As[kk][ty * TM];
            *(float4*)&a[4] = *(float4*)&As[kk][ty * TM + 4];
            *(float4*)&b[0] = *(float4*)&Bs[kk][tx * TN];
            *(float4*)&b[4] = *(float4*)&Bs[kk][tx * TN + 4];
#pragma unroll
            for (int i = 0; i < TM; i++)
#pragma unroll
                for (int j = 0; j < TN; j++)
                    acc[i][j] += a[i] * b[j];
        }
        __syncthreads();
    }

    // epilogue: add bias, store
#pragma unroll
    for (int i = 0; i < TM; i++) {
        int r = row0 + ty * TM + i;
#pragma unroll
        for (int j = 0; j < TN; j += 4) {
            int c = col0 + tx * TN + j;
            float4 v;
            v.x = acc[i][j + 0] + bias[c + 0];
            v.y = acc[i][j + 1] + bias[c + 1];
            v.z = acc[i][j + 2] + bias[c + 2];
            v.w = acc[i][j + 3] + bias[c + 3];
            *(float4*)(Cout + (size_t)r * N + c) = v;
        }
    }
}

// ---------------- causal flash attention, fp32, 1 query/thread ----------------
// grid: (B*H, T/128), block: 128 threads. K/V tiles of 64 keys in SMEM.
#define QROWS 128
#define KTILE 64

__global__ __launch_bounds__(QROWS, 2) void attn_kernel(
    const float* __restrict__ qkv, float* __restrict__ y)
{
    __shared__ float Ks[KTILE * HD_];
    __shared__ float Vs[KTILE * HD_];

    const int tid = threadIdx.x;
    const int bh  = blockIdx.x;
    const int b   = bh / H_;
    const int h   = bh % H_;
    // reverse order: heavy (late) query tiles launch first
    const int qt  = (gridDim.y - 1) - blockIdx.y;
    const int qi  = qt * QROWS + tid;

    const float* base = qkv + (size_t)b * T_ * C3_;

    // load & pre-scale q (scale = 1/sqrt(64) = 0.125)
    float q[HD_];
    {
        const float4* qp = (const float4*)(base + (size_t)qi * C3_ + h * HD_);
#pragma unroll
        for (int d4 = 0; d4 < HD_ / 4; d4++) {
            float4 v = qp[d4];
            q[d4 * 4 + 0] = v.x * 0.125f;
            q[d4 * 4 + 1] = v.y * 0.125f;
            q[d4 * 4 + 2] = v.z * 0.125f;
            q[d4 * 4 + 3] = v.w * 0.125f;
        }
    }

    float o[HD_];
#pragma unroll
    for (int d = 0; d < HD_; d++) o[d] = 0.f;
    float m = -INFINITY;
    float l = 0.f;

    const int q_hi = qt * QROWS + (QROWS - 1);  // max query in this block

    for (int kt = 0; kt * KTILE <= q_hi; kt++) {
        __syncthreads();
        // cooperative load of K and V tiles (64 keys x 64 dims each)
        // 64*16 = 1024 float4 per tile; 128 threads -> 8 float4 each
#pragma unroll
        for (int it = 0; it < 8; it++) {
            int idx = tid + it * QROWS;       // 0..1023
            int r   = idx >> 4;               // key row 0..63
            int c4  = (idx & 15) * 4;         // 0..60
            const float* grow = base + (size_t)(kt * KTILE + r) * C3_ + h * HD_;
            *(float4*)&Ks[r * HD_ + c4] = *(const float4*)(grow + C_  + c4);
            *(float4*)&Vs[r * HD_ + c4] = *(const float4*)(grow + 2*C_ + c4);
        }
        __syncthreads();

        const int jmax = qi - kt * KTILE + 1;     // #valid keys for this thread
        const int jend = jmax < KTILE ? jmax : KTILE;

        for (int j = 0; j < jend; j++) {
            // s = q . k_j  (k broadcast from SMEM)
            float s0 = 0.f, s1 = 0.f, s2 = 0.f, s3 = 0.f;
            const float4* kr = (const float4*)&Ks[j * HD_];
#pragma unroll
            for (int d4 = 0; d4 < HD_ / 4; d4++) {
                float4 kv = kr[d4];
                s0 += q[d4 * 4 + 0] * kv.x;
                s1 += q[d4 * 4 + 1] * kv.y;
                s2 += q[d4 * 4 + 2] * kv.z;
                s3 += q[d4 * 4 + 3] * kv.w;
            }
            float s = (s0 + s1) + (s2 + s3);

            const float4* vr = (const float4*)&Vs[j * HD_];
            if (s <= m) {
                float p = __expf(s - m);
                l += p;
#pragma unroll
                for (int d4 = 0; d4 < HD_ / 4; d4++) {
                    float4 vv = vr[d4];
                    o[d4 * 4 + 0] += p * vv.x;
                    o[d4 * 4 + 1] += p * vv.y;
                    o[d4 * 4 + 2] += p * vv.z;
                    o[d4 * 4 + 3] += p * vv.w;
                }
            } else {
                float alpha = __expf(m - s);  // exp(-inf)=0 handles first key
                m = s;
                l = l * alpha + 1.f;
#pragma unroll
                for (int d4 = 0; d4 < HD_ / 4; d4++) {
                    float4 vv = vr[d4];
                    o[d4 * 4 + 0] = o[d4 * 4 + 0] * alpha + vv.x;
                    o[d4 * 4 + 1] = o[d4 * 4 + 1] * alpha + vv.y;
                    o[d4 * 4 + 2] = o[d4 * 4 + 2] * alpha + vv.z;
                    o[d4 * 4 + 3] = o[d4 * 4 + 3] * alpha + vv.w;
                }
            }
        }
    }

    // write y[b, qi, h*64 + d] = o[d]/l
    const float inv = 1.f / l;
    float* yrow = y + (size_t)(b * T_ + qi) * C_ + h * HD_;
#pragma unroll
    for (int d4 = 0; d4 < HD_ / 4; d4++) {
        float4 v;
        v.x = o[d4 * 4 + 0] * inv;
        v.y = o[d4 * 4 + 1] * inv;
        v.z = o[d4 * 4 + 2] * inv;
        v.w = o[d4 * 4 + 3] * inv;
        *(float4*)(yrow + d4 * 4) = v;
    }
}

// ---------------- launch ----------------
extern "C" void kernel_launch(void* const* d_in, const int* in_sizes, int n_in,
                              void* d_out, int out_size)
{
    const float* x     = (const float*)d_in[0];   // [B,T,C]
    const float* w_qkv = (const float*)d_in[1];   // [C,3C]
    const float* b_qkv = (const float*)d_in[2];   // [3C]
    const float* w_out = (const float*)d_in[3];   // [C,C]
    const float* b_out = (const float*)d_in[4];   // [C]
    float* out = (float*)d_out;                   // [B,T,C]

    float* qkv_ptr = nullptr;
    float* y_ptr   = nullptr;
    cudaGetSymbolAddress((void**)&qkv_ptr, g_qkv);
    cudaGetSymbolAddress((void**)&y_ptr,   g_y);

    // 1) qkv = x @ w_qkv + b_qkv   (M=4096, N=3072, K=1024)
    {
        dim3 grid(C3_ / BN, M_ / BM);
        gemm_bias_kernel<<<grid, 256>>>(x, w_qkv, b_qkv, qkv_ptr, M_, C3_, C_);
    }

    // 2) causal attention -> y  [B,T,C]
    {
        dim3 grid(B_ * H_, T_ / QROWS);
        attn_kernel<<<grid, QROWS>>>(qkv_ptr, y_ptr);
    }

    // 3) out = y @ w_out + b_out  (M=4096, N=1024, K=1024)
    {
        dim3 grid(C_ / BN, M_ / BM);
        gemm_bias_kernel<<<grid, 256>>>(y_ptr, w_out, b_out, out, M_, C_, C_);
    }
}

// round 3
// speedup vs baseline: 1.1554x; 1.1554x over previous
#include <cuda_runtime.h>
#include <cuda_bf16.h>
#include <math.h>
#include <stdint.h>

// Problem dims (fixed by the dataset)
#define B_   2
#define T_   2048
#define C_   1024
#define H_   16
#define HD_  64
#define C3_  (3*C_)
#define M_   (B_*T_)          // 4096 rows

// ---------------- scratch (no cudaMalloc allowed) ----------------
__device__ float g_qkv[(size_t)M_ * C3_];         // [B*T, 3C]
__device__ float g_y  [(size_t)M_ * C_];          // [B*T, C]
__device__ __nv_bfloat16 g_x_hi[(size_t)M_ * C_];
__device__ __nv_bfloat16 g_x_lo[(size_t)M_ * C_];
__device__ __nv_bfloat16 g_y_hi[(size_t)M_ * C_];
__device__ __nv_bfloat16 g_y_lo[(size_t)M_ * C_];
__device__ __nv_bfloat16 g_wqkvT_hi[(size_t)C3_ * C_];  // [N=3C][K=C]
__device__ __nv_bfloat16 g_wqkvT_lo[(size_t)C3_ * C_];
__device__ __nv_bfloat16 g_woutT_hi[(size_t)C_ * C_];   // [N=C][K=C]
__device__ __nv_bfloat16 g_woutT_lo[(size_t)C_ * C_];

// ---------------- prep: elementwise fp32 -> (hi, lo) bf16 ----------------
__global__ void split_f32_kernel(const float* __restrict__ src,
                                 __nv_bfloat16* __restrict__ hi,
                                 __nv_bfloat16* __restrict__ lo, int n)
{
    int i = blockIdx.x * blockDim.x + threadIdx.x;
    int stride = gridDim.x * blockDim.x;
    for (; i < n; i += stride) {
        float v = src[i];
        __nv_bfloat16 h = __float2bfloat16(v);
        hi[i] = h;
        lo[i] = __float2bfloat16(v - __bfloat162float(h));
    }
}

// ---------------- prep: transpose + split. src [K][N] fp32 -> dst [N][K] bf16 hi/lo
__global__ void split_transpose_kernel(const float* __restrict__ src,
                                       __nv_bfloat16* __restrict__ hi,
                                       __nv_bfloat16* __restrict__ lo,
                                       int K, int N)
{
    __shared__ float ts[32][33];
    const int n0 = blockIdx.x * 32;
    const int k0 = blockIdx.y * 32;
    const int tx = threadIdx.x;      // 0..31
    const int ty = threadIdx.y;      // 0..7
#pragma unroll
    for (int i = 0; i < 4; i++) {
        int k = k0 + ty + i * 8;
        ts[ty + i * 8][tx] = src[(size_t)k * N + n0 + tx];
    }
    __syncthreads();
#pragma unroll
    for (int i = 0; i < 4; i++) {
        int n = n0 + ty + i * 8;
        float v = ts[tx][ty + i * 8];
        __nv_bfloat16 h = __float2bfloat16(v);
        size_t idx = (size_t)n * K + k0 + tx;
        hi[idx] = h;
        lo[idx] = __float2bfloat16(v - __bfloat162float(h));
    }
}

// ================= bf16 split-2 tensor-core GEMM =================
// C = A[M,K] @ W[K,N] + bias, where A is given as (Ahi+Alo) bf16 [M][K]
// and W as (Bhi+Blo) bf16 stored TRANSPOSED [N][K].
// D += Ahi*Bhi + Ahi*Blo + Alo*Bhi   (fp32 accumulate)
// Tiles: BM=128, BN=128, BK=32. 256 threads = 8 warps (2x4), warp tile 64x32.

#define GBM 128
#define GBN 128
#define GBK 32
#define TSTRIDE 20          // words (uint32 = 2 bf16) per SMEM tile row
#define TILE_WORDS (128 * TSTRIDE)   // 2560 words = 10240 B per tile

__device__ __forceinline__ uint32_t smem_u32(const void* p) {
    return (uint32_t)__cvta_generic_to_shared(p);
}
__device__ __forceinline__ void cp_async16(void* s, const void* g) {
    asm volatile("cp.async.cg.shared.global [%0], [%1], 16;\n"
                 :: "r"(smem_u32(s)), "l"(g));
}
__device__ __forceinline__ void cp_commit() {
    asm volatile("cp.async.commit_group;\n" ::);
}
__device__ __forceinline__ void cp_wait0() {
    asm volatile("cp.async.wait_group 0;\n" ::);
}
__device__ __forceinline__ void mma_bf16(float* d, const uint32_t* a, const uint32_t* b) {
    asm volatile(
        "mma.sync.aligned.m16n8k16.row.col.f32.bf16.bf16.f32 "
        "{%0,%1,%2,%3}, {%4,%5,%6,%7}, {%8,%9}, {%0,%1,%2,%3};\n"
        : "+f"(d[0]), "+f"(d[1]), "+f"(d[2]), "+f"(d[3])
        : "r"(a[0]), "r"(a[1]), "r"(a[2]), "r"(a[3]),
          "r"(b[0]), "r"(b[1]));
}

__global__ __launch_bounds__(256) void gemm_bf16x2_kernel(
    const __nv_bfloat16* __restrict__ Ahi, const __nv_bfloat16* __restrict__ Alo,
    const __nv_bfloat16* __restrict__ Bhi, const __nv_bfloat16* __restrict__ Blo,
    const float* __restrict__ bias, float* __restrict__ Cout,
    int M, int N, int K)
{
    extern __shared__ uint32_t sm[];
    // layout: [buf][tile], tiles: 0=Ahi 1=Alo 2=Bhi 3=Blo
    uint32_t* tiles[2][4];
#pragma unroll
    for (int b = 0; b < 2; b++)
#pragma unroll
        for (int t = 0; t < 4; t++)
            tiles[b][t] = sm + (b * 4 + t) * TILE_WORDS;

    const int tid  = threadIdx.x;
    const int wid  = tid >> 5;
    const int lane = tid & 31;
    const int g    = lane >> 2;   // 0..7
    const int q    = lane & 3;    // 0..3
    const int row0 = blockIdx.y * GBM;
    const int col0 = blockIdx.x * GBN;
    const int wm   = (wid & 1) * 64;   // warp M offset
    const int wn   = (wid >> 1) * 32;  // warp N offset

    float acc[4][4][4];
#pragma unroll
    for (int mi = 0; mi < 4; mi++)
#pragma unroll
        for (int ni = 0; ni < 4; ni++)
#pragma unroll
            for (int r = 0; r < 4; r++) acc[mi][ni][r] = 0.f;

    // tile loader: each tile is 128 rows x 32 bf16 (64 B = 4 cp16 per row)
    const __nv_bfloat16* srcs[4] = {Ahi, Alo, Bhi, Blo};
    auto load_tile = [&](int kt, int buf) {
        const int k0 = kt * GBK;
#pragma unroll
        for (int t = 0; t < 4; t++) {
            const __nv_bfloat16* base = srcs[t] +
                (size_t)((t < 2) ? row0 : col0) * K + k0;
#pragma unroll
            for (int it = 0; it < 2; it++) {
                int idx = tid + it * 256;            // 0..511
                int r   = idx >> 2;                  // row 0..127
                int f   = idx & 3;                   // 16B chunk 0..3
                cp_async16(&tiles[buf][t][r * TSTRIDE + f * 4],
                           base + (size_t)r * K + f * 8);
            }
        }
        cp_commit();
    };

    load_tile(0, 0);
    cp_wait0();
    __syncthreads();

    const int KT = K / GBK;
    for (int kt = 0; kt < KT; kt++) {
        const int buf = kt & 1;
        if (kt + 1 < KT) load_tile(kt + 1, buf ^ 1);

        const uint32_t* sAh = tiles[buf][0];
        const uint32_t* sAl = tiles[buf][1];
        const uint32_t* sBh = tiles[buf][2];
        const uint32_t* sBl = tiles[buf][3];

#pragma unroll
        for (int ks = 0; ks < 2; ks++) {           // two k16 steps per BK=32
            const int kw = ks * 8 + q;             // word col within row
            uint32_t ah[4][4], al[4][4], bh[4][2], bl[4][2];
#pragma unroll
            for (int mi = 0; mi < 4; mi++) {
                int r  = wm + mi * 16 + g;
                int b0 = r * TSTRIDE + kw;
                int b1 = (r + 8) * TSTRIDE + kw;
                ah[mi][0] = sAh[b0];     ah[mi][1] = sAh[b1];
                ah[mi][2] = sAh[b0 + 4]; ah[mi][3] = sAh[b1 + 4];
                al[mi][0] = sAl[b0];     al[mi][1] = sAl[b1];
                al[mi][2] = sAl[b0 + 4]; al[mi][3] = sAl[b1 + 4];
            }
#pragma unroll
            for (int ni = 0; ni < 4; ni++) {
                int n  = wn + ni * 8 + g;
                int b0 = n * TSTRIDE + kw;
                bh[ni][0] = sBh[b0]; bh[ni][1] = sBh[b0 + 4];
                bl[ni][0] = sBl[b0]; bl[ni][1] = sBl[b0 + 4];
            }
#pragma unroll
            for (int mi = 0; mi < 4; mi++)
#pragma unroll
                for (int ni = 0; ni < 4; ni++) {
                    mma_bf16(acc[mi][ni], ah[mi], bh[ni]);
                    mma_bf16(acc[mi][ni], ah[mi], bl[ni]);
                    mma_bf16(acc[mi][ni], al[mi], bh[ni]);
                }
        }

        if (kt + 1 < KT) cp_wait0();
        __syncthreads();
    }

    // epilogue: bias + store (float2, c = col0+wn+ni*8+2q even)
#pragma unroll
    for (int mi = 0; mi < 4; mi++) {
#pragma unroll
        for (int ni = 0; ni < 4; ni++) {
            int r = row0 + wm + mi * 16 + g;
            int c = col0 + wn + ni * 8 + 2 * q;
            float b0 = bias[c], b1 = bias[c + 1];
            float2 v0 = make_float2(acc[mi][ni][0] + b0, acc[mi][ni][1] + b1);
            float2 v1 = make_float2(acc[mi][ni][2] + b0, acc[mi][ni][3] + b1);
            *(float2*)(Cout + (size_t)r * N + c)       = v0;
            *(float2*)(Cout + (size_t)(r + 8) * N + c) = v1;
        }
    }
}

// ---------------- causal flash attention, fp32, 1 query/thread ----------------
#define QROWS 128
#define KTILE 64

__global__ __launch_bounds__(QROWS) void attn_kernel(
    const float* __restrict__ qkv, float* __restrict__ y)
{
    __shared__ float Ks[KTILE * HD_];
    __shared__ float Vs[KTILE * HD_];

    const int tid = threadIdx.x;
    const int bh  = blockIdx.x;
    const int b   = bh / H_;
    const int h   = bh % H_;
    const int qt  = (gridDim.y - 1) - blockIdx.y;   // heavy tiles first
    const int qi  = qt * QROWS + tid;

    const float* base = qkv + (size_t)b * T_ * C3_;

    float qr[HD_];
    {
        const float4* qp = (const float4*)(base + (size_t)qi * C3_ + h * HD_);
#pragma unroll
        for (int d4 = 0; d4 < HD_ / 4; d4++) {
            float4 v = qp[d4];
            qr[d4 * 4 + 0] = v.x * 0.125f;
            qr[d4 * 4 + 1] = v.y * 0.125f;
            qr[d4 * 4 + 2] = v.z * 0.125f;
            qr[d4 * 4 + 3] = v.w * 0.125f;
        }
    }

    float o[HD_];
#pragma unroll
    for (int d = 0; d < HD_; d++) o[d] = 0.f;
    float m = -INFINITY;
    float l = 0.f;

    const int q_hi = qt * QROWS + (QROWS - 1);

    for (int kt = 0; kt * KTILE <= q_hi; kt++) {
        __syncthreads();
#pragma unroll
        for (int it = 0; it < 8; it++) {
            int idx = tid + it * QROWS;       // 0..1023
            int r   = idx >> 4;
            int c4  = (idx & 15) * 4;
            const float* grow = base + (size_t)(kt * KTILE + r) * C3_ + h * HD_;
            *(float4*)&Ks[r * HD_ + c4] = *(const float4*)(grow + C_   + c4);
            *(float4*)&Vs[r * HD_ + c4] = *(const float4*)(grow + 2*C_ + c4);
        }
        __syncthreads();

        const int valid = qi - kt * KTILE + 1;
        const int jend  = valid < KTILE ? valid : KTILE;
        if (jend <= 0) continue;

        for (int j0 = 0; j0 < jend; j0 += 8) {
            float s[8];
#pragma unroll
            for (int jj = 0; jj < 8; jj++) {
                const int j = j0 + jj;
                const float4* kr = (const float4*)&Ks[j * HD_];
                float s0 = 0.f, s1 = 0.f, s2 = 0.f, s3 = 0.f;
#pragma unroll
                for (int d4 = 0; d4 < HD_ / 4; d4++) {
                    float4 kv = kr[d4];
                    s0 += qr[d4 * 4 + 0] * kv.x;
                    s1 += qr[d4 * 4 + 1] * kv.y;
                    s2 += qr[d4 * 4 + 2] * kv.z;
                    s3 += qr[d4 * 4 + 3] * kv.w;
                }
                s[jj] = (j < jend) ? ((s0 + s1) + (s2 + s3)) : -INFINITY;
            }

            float t01 = fmaxf(s[0], s[1]), t23 = fmaxf(s[2], s[3]);
            float t45 = fmaxf(s[4], s[5]), t67 = fmaxf(s[6], s[7]);
            float tmax = fmaxf(fmaxf(t01, t23), fmaxf(t45, t67));

            if (tmax > m) {
                float alpha = __expf(m - tmax);
                m = tmax;
                l *= alpha;
#pragma unroll
                for (int d = 0; d < HD_; d++) o[d] *= alpha;
            }

#pragma unroll
            for (int jj = 0; jj < 8; jj++) {
                float p = __expf(s[jj] - m);
                l += p;
                const float4* vr = (const float4*)&Vs[(j0 + jj) * HD_];
#pragma unroll
                for (int d4 = 0; d4 < HD_ / 4; d4++) {
                    float4 vv = vr[d4];
                    o[d4 * 4 + 0] += p * vv.x;
                    o[d4 * 4 + 1] += p * vv.y;
                    o[d4 * 4 + 2] += p * vv.z;
                    o[d4 * 4 + 3] += p * vv.w;
                }
            }
        }
    }

    const float inv = 1.f / l;
    float* yrow = y + (size_t)(b * T_ + qi) * C_ + h * HD_;
#pragma unroll
    for (int d4 = 0; d4 < HD_ / 4; d4++) {
        float4 v;
        v.x = o[d4 * 4 + 0] * inv;
        v.y = o[d4 * 4 + 1] * inv;
        v.z = o[d4 * 4 + 2] * inv;
        v.w = o[d4 * 4 + 3] * inv;
        *(float4*)(yrow + d4 * 4) = v;
    }
}

// ---------------- launch ----------------
extern "C" void kernel_launch(void* const* d_in, const int* in_sizes, int n_in,
                              void* d_out, int out_size)
{
    const float* x     = (const float*)d_in[0];   // [B,T,C]
    const float* w_qkv = (const float*)d_in[1];   // [C,3C]
    const float* b_qkv = (const float*)d_in[2];   // [3C]
    const float* w_out = (const float*)d_in[3];   // [C,C]
    const float* b_out = (const float*)d_in[4];   // [C]
    float* out = (float*)d_out;                   // [B,T,C]

    float* qkv_ptr; float* y_ptr;
    __nv_bfloat16 *xhi, *xlo, *yhi, *ylo, *wqhi, *wqlo, *wohi, *wolo;
    cudaGetSymbolAddress((void**)&qkv_ptr, g_qkv);
    cudaGetSymbolAddress((void**)&y_ptr,   g_y);
    cudaGetSymbolAddress((void**)&xhi, g_x_hi);
    cudaGetSymbolAddress((void**)&xlo, g_x_lo);
    cudaGetSymbolAddress((void**)&yhi, g_y_hi);
    cudaGetSymbolAddress((void**)&ylo, g_y_lo);
    cudaGetSymbolAddress((void**)&wqhi, g_wqkvT_hi);
    cudaGetSymbolAddress((void**)&wqlo, g_wqkvT_lo);
    cudaGetSymbolAddress((void**)&wohi, g_woutT_hi);
    cudaGetSymbolAddress((void**)&wolo, g_woutT_lo);

    static bool smem_set = false;
    if (!smem_set) {
        cudaFuncSetAttribute(gemm_bf16x2_kernel,
                             cudaFuncAttributeMaxDynamicSharedMemorySize,
                             8 * TILE_WORDS * 4);
        smem_set = true;
    }
    const int gemm_smem = 8 * TILE_WORDS * 4;   // 81920 B

    // 0a) split x -> bf16 hi/lo
    split_f32_kernel<<<1024, 256>>>(x, xhi, xlo, M_ * C_);
    // 0b) transpose+split weights: [K][N] -> [N][K]
    {
        dim3 grid(C3_ / 32, C_ / 32), blk(32, 8);
        split_transpose_kernel<<<grid, blk>>>(w_qkv, wqhi, wqlo, C_, C3_);
    }
    {
        dim3 grid(C_ / 32, C_ / 32), blk(32, 8);
        split_transpose_kernel<<<grid, blk>>>(w_out, wohi, wolo, C_, C_);
    }

    // 1) qkv = x @ w_qkv + b_qkv   (M=4096, N=3072, K=1024)
    {
        dim3 grid(C3_ / GBN, M_ / GBM);
        gemm_bf16x2_kernel<<<grid, 256, gemm_smem>>>(
            xhi, xlo, wqhi, wqlo, b_qkv, qkv_ptr, M_, C3_, C_);
    }

    // 2) causal attention -> y  [B,T,C]
    {
        dim3 grid(B_ * H_, T_ / QROWS);
        attn_kernel<<<grid, QROWS>>>(qkv_ptr, y_ptr);
    }

    // 2b) split y
    split_f32_kernel<<<1024, 256>>>(y_ptr, yhi, ylo, M_ * C_);

    // 3) out = y @ w_out + b_out  (M=4096, N=1024, K=1024)
    {
        dim3 grid(C_ / GBN, M_ / GBM);
        gemm_bf16x2_kernel<<<grid, 256, gemm_smem>>>(
            yhi, ylo, wohi, wolo, b_out, out, M_, C_, C_);
    }
}

// round 4
// speedup vs baseline: 2.3491x; 2.0332x over previous
#include <cuda_runtime.h>
#include <cuda_bf16.h>
#include <math.h>
#include <stdint.h>

// Problem dims (fixed by the dataset)
#define B_   2
#define T_   2048
#define C_   1024
#define H_   16
#define HD_  64
#define C3_  (3*C_)
#define M_   (B_*T_)          // 4096 rows

// ---------------- scratch (no cudaMalloc allowed) ----------------
__device__ float g_qkv[(size_t)M_ * C3_];         // [B*T, 3C]
__device__ float g_y  [(size_t)M_ * C_];          // [B*T, C]
__device__ __nv_bfloat16 g_x_hi[(size_t)M_ * C_];
__device__ __nv_bfloat16 g_x_lo[(size_t)M_ * C_];
__device__ __nv_bfloat16 g_y_hi[(size_t)M_ * C_];
__device__ __nv_bfloat16 g_y_lo[(size_t)M_ * C_];
__device__ __nv_bfloat16 g_wqkvT_hi[(size_t)C3_ * C_];  // [N=3C][K=C]
__device__ __nv_bfloat16 g_wqkvT_lo[(size_t)C3_ * C_];
__device__ __nv_bfloat16 g_woutT_hi[(size_t)C_ * C_];   // [N=C][K=C]
__device__ __nv_bfloat16 g_woutT_lo[(size_t)C_ * C_];

// ---------------- helpers ----------------
__device__ __forceinline__ uint32_t smem_u32(const void* p) {
    return (uint32_t)__cvta_generic_to_shared(p);
}
__device__ __forceinline__ void cp_async16(void* s, const void* g) {
    asm volatile("cp.async.cg.shared.global [%0], [%1], 16;\n"
                 :: "r"(smem_u32(s)), "l"(g));
}
__device__ __forceinline__ void cp_commit() {
    asm volatile("cp.async.commit_group;\n" ::);
}
__device__ __forceinline__ void cp_wait0() {
    asm volatile("cp.async.wait_group 0;\n" ::);
}
__device__ __forceinline__ void mma_bf16(float* d, const uint32_t* a, const uint32_t* b) {
    asm volatile(
        "mma.sync.aligned.m16n8k16.row.col.f32.bf16.bf16.f32 "
        "{%0,%1,%2,%3}, {%4,%5,%6,%7}, {%8,%9}, {%0,%1,%2,%3};\n"
        : "+f"(d[0]), "+f"(d[1]), "+f"(d[2]), "+f"(d[3])
        : "r"(a[0]), "r"(a[1]), "r"(a[2]), "r"(a[3]),
          "r"(b[0]), "r"(b[1]));
}
// pack (lo_elem, hi_elem) floats into bf16x2 word (lo in low half)
__device__ __forceinline__ uint32_t pack_bf16x2(float lo, float hi) {
    uint32_t r;
    asm("cvt.rn.bf16x2.f32 %0, %1, %2;" : "=r"(r) : "f"(hi), "f"(lo));
    return r;
}
__device__ __forceinline__ uint32_t pack_hi_pair(float a, float b,
                                                 float& ra, float& rb) {
    // hi = bf16(a),bf16(b); residuals returned
    uint32_t w = pack_bf16x2(a, b);
    __nv_bfloat162 h = *reinterpret_cast<__nv_bfloat162*>(&w);
    ra = a - __bfloat162float(h.x);
    rb = b - __bfloat162float(h.y);
    return w;
}

// ---------------- prep: elementwise fp32 -> (hi, lo) bf16 ----------------
__global__ void split_f32_kernel(const float* __restrict__ src,
                                 __nv_bfloat16* __restrict__ hi,
                                 __nv_bfloat16* __restrict__ lo, int n)
{
    int i = blockIdx.x * blockDim.x + threadIdx.x;
    int stride = gridDim.x * blockDim.x;
    for (; i < n; i += stride) {
        float v = src[i];
        __nv_bfloat16 h = __float2bfloat16(v);
        hi[i] = h;
        lo[i] = __float2bfloat16(v - __bfloat162float(h));
    }
}

// ---------------- prep: transpose + split. src [K][N] fp32 -> dst [N][K] bf16 hi/lo
__global__ void split_transpose_kernel(const float* __restrict__ src,
                                       __nv_bfloat16* __restrict__ hi,
                                       __nv_bfloat16* __restrict__ lo,
                                       int K, int N)
{
    __shared__ float ts[32][33];
    const int n0 = blockIdx.x * 32;
    const int k0 = blockIdx.y * 32;
    const int tx = threadIdx.x;      // 0..31
    const int ty = threadIdx.y;      // 0..7
#pragma unroll
    for (int i = 0; i < 4; i++) {
        int k = k0 + ty + i * 8;
        ts[ty + i * 8][tx] = src[(size_t)k * N + n0 + tx];
    }
    __syncthreads();
#pragma unroll
    for (int i = 0; i < 4; i++) {
        int n = n0 + ty + i * 8;
        float v = ts[tx][ty + i * 8];
        __nv_bfloat16 h = __float2bfloat16(v);
        size_t idx = (size_t)n * K + k0 + tx;
        hi[idx] = h;
        lo[idx] = __float2bfloat16(v - __bfloat162float(h));
    }
}

// ================= bf16 split-2 tensor-core GEMM =================
#define GBM 128
#define GBN 128
#define GBK 32
#define TSTRIDE 20
#define TILE_WORDS (128 * TSTRIDE)

__global__ __launch_bounds__(256, 2) void gemm_bf16x2_kernel(
    const __nv_bfloat16* __restrict__ Ahi, const __nv_bfloat16* __restrict__ Alo,
    const __nv_bfloat16* __restrict__ Bhi, const __nv_bfloat16* __restrict__ Blo,
    const float* __restrict__ bias, float* __restrict__ Cout,
    int M, int N, int K)
{
    extern __shared__ uint32_t sm[];
    uint32_t* tiles[2][4];
#pragma unroll
    for (int b = 0; b < 2; b++)
#pragma unroll
        for (int t = 0; t < 4; t++)
            tiles[b][t] = sm + (b * 4 + t) * TILE_WORDS;

    const int tid  = threadIdx.x;
    const int wid  = tid >> 5;
    const int lane = tid & 31;
    const int g    = lane >> 2;
    const int q    = lane & 3;
    const int row0 = blockIdx.y * GBM;
    const int col0 = blockIdx.x * GBN;
    const int wm   = (wid & 1) * 64;
    const int wn   = (wid >> 1) * 32;

    float acc[4][4][4];
#pragma unroll
    for (int mi = 0; mi < 4; mi++)
#pragma unroll
        for (int ni = 0; ni < 4; ni++)
#pragma unroll
            for (int r = 0; r < 4; r++) acc[mi][ni][r] = 0.f;

    const __nv_bfloat16* srcs[4] = {Ahi, Alo, Bhi, Blo};
    auto load_tile = [&](int kt, int buf) {
        const int k0 = kt * GBK;
#pragma unroll
        for (int t = 0; t < 4; t++) {
            const __nv_bfloat16* base = srcs[t] +
                (size_t)((t < 2) ? row0 : col0) * K + k0;
#pragma unroll
            for (int it = 0; it < 2; it++) {
                int idx = tid + it * 256;
                int r   = idx >> 2;
                int f   = idx & 3;
                cp_async16(&tiles[buf][t][r * TSTRIDE + f * 4],
                           base + (size_t)r * K + f * 8);
            }
        }
        cp_commit();
    };

    load_tile(0, 0);
    cp_wait0();
    __syncthreads();

    const int KT = K / GBK;
    for (int kt = 0; kt < KT; kt++) {
        const int buf = kt & 1;
        if (kt + 1 < KT) load_tile(kt + 1, buf ^ 1);

        const uint32_t* sAh = tiles[buf][0];
        const uint32_t* sAl = tiles[buf][1];
        const uint32_t* sBh = tiles[buf][2];
        const uint32_t* sBl = tiles[buf][3];

#pragma unroll
        for (int ks = 0; ks < 2; ks++) {
            const int kw = ks * 8 + q;
            uint32_t ah[4][4], al[4][4], bh[4][2], bl[4][2];
#pragma unroll
            for (int mi = 0; mi < 4; mi++) {
                int r  = wm + mi * 16 + g;
                int b0 = r * TSTRIDE + kw;
                int b1 = (r + 8) * TSTRIDE + kw;
                ah[mi][0] = sAh[b0];     ah[mi][1] = sAh[b1];
                ah[mi][2] = sAh[b0 + 4]; ah[mi][3] = sAh[b1 + 4];
                al[mi][0] = sAl[b0];     al[mi][1] = sAl[b1];
                al[mi][2] = sAl[b0 + 4]; al[mi][3] = sAl[b1 + 4];
            }
#pragma unroll
            for (int ni = 0; ni < 4; ni++) {
                int n  = wn + ni * 8 + g;
                int b0 = n * TSTRIDE + kw;
                bh[ni][0] = sBh[b0]; bh[ni][1] = sBh[b0 + 4];
                bl[ni][0] = sBl[b0]; bl[ni][1] = sBl[b0 + 4];
            }
#pragma unroll
            for (int mi = 0; mi < 4; mi++)
#pragma unroll
                for (int ni = 0; ni < 4; ni++) {
                    mma_bf16(acc[mi][ni], ah[mi], bh[ni]);
                    mma_bf16(acc[mi][ni], ah[mi], bl[ni]);
                    mma_bf16(acc[mi][ni], al[mi], bh[ni]);
                }
        }

        if (kt + 1 < KT) cp_wait0();
        __syncthreads();
    }

#pragma unroll
    for (int mi = 0; mi < 4; mi++) {
#pragma unroll
        for (int ni = 0; ni < 4; ni++) {
            int r = row0 + wm + mi * 16 + g;
            int c = col0 + wn + ni * 8 + 2 * q;
            float b0 = bias[c], b1 = bias[c + 1];
            float2 v0 = make_float2(acc[mi][ni][0] + b0, acc[mi][ni][1] + b1);
            float2 v1 = make_float2(acc[mi][ni][2] + b0, acc[mi][ni][3] + b1);
            *(float2*)(Cout + (size_t)r * N + c)       = v0;
            *(float2*)(Cout + (size_t)(r + 8) * N + c) = v1;
        }
    }
}

// ================= MMA flash attention (bf16 split, fp32 softmax) =================
// Block: 256 threads = 8 warps. Block covers 128 queries of one (b,h).
// Warp w handles query rows qb + w*16 .. +15. Key/V tiles of 64 in SMEM.
// SMEM word layout (uint32 sm[9216] = 36 KB):
//   main loop: Khi @0 (64 rows x 36 wds), Klo @2304, VThi @4608, VTlo @6912
//   prologue:  Qhi rows 0..127 stride 36 @0, Qlo @4608 (then overwritten)
#define AT_STRIDE 36   // words per 64-dim row: (36*g+q)%32 = 4g+q conflict-free

__global__ __launch_bounds__(256) void attn_mma_kernel(
    const float* __restrict__ qkv, float* __restrict__ y)
{
    __shared__ uint32_t sm[9216];

    const int tid  = threadIdx.x;
    const int w    = tid >> 5;
    const int lane = tid & 31;
    const int g    = lane >> 2;
    const int q    = lane & 3;
    const int bh   = blockIdx.x;
    const int b    = bh >> 4;          // H_=16
    const int h    = bh & 15;
    const int qt   = (gridDim.y - 1) - blockIdx.y;   // heavy blocks first
    const int qb   = qt * 128;

    const float* base = qkv + (size_t)b * T_ * C3_;

    // ---- stage Q (scaled by 1/sqrt(64)=0.125) as hi/lo bf16 ----
#pragma unroll
    for (int it = 0; it < 8; it++) {
        int idx = tid + it * 256;            // 0..2047
        int row = idx >> 4;
        int c4  = (idx & 15) * 4;
        float4 v = *(const float4*)(base + (size_t)(qb + row) * C3_ + h * HD_ + c4);
        float r0, r1, r2, r3;
        uint32_t h01 = pack_hi_pair(v.x * 0.125f, v.y * 0.125f, r0, r1);
        uint32_t h23 = pack_hi_pair(v.z * 0.125f, v.w * 0.125f, r2, r3);
        sm[row * AT_STRIDE + c4 / 2]     = h01;
        sm[row * AT_STRIDE + c4 / 2 + 1] = h23;
        sm[4608 + row * AT_STRIDE + c4 / 2]     = pack_bf16x2(r0, r1);
        sm[4608 + row * AT_STRIDE + c4 / 2 + 1] = pack_bf16x2(r2, r3);
    }
    __syncthreads();

    // ---- Q fragments to registers ----
    uint32_t qh[4][4], ql[4][4];
    {
        const int r0 = w * 16 + g;
        const int r1 = r0 + 8;
#pragma unroll
        for (int ks = 0; ks < 4; ks++) {
            int o0 = r0 * AT_STRIDE + ks * 8 + q;
            int o1 = r1 * AT_STRIDE + ks * 8 + q;
            qh[ks][0] = sm[o0];     qh[ks][1] = sm[o1];
            qh[ks][2] = sm[o0 + 4]; qh[ks][3] = sm[o1 + 4];
            ql[ks][0] = sm[4608 + o0];     ql[ks][1] = sm[4608 + o1];
            ql[ks][2] = sm[4608 + o0 + 4]; ql[ks][3] = sm[4608 + o1 + 4];
        }
    }

    uint32_t* Khi  = sm;
    uint32_t* Klo  = sm + 2304;
    uint32_t* VThi = sm + 4608;
    uint32_t* VTlo = sm + 6912;
    __nv_bfloat16* vth = (__nv_bfloat16*)VThi;
    __nv_bfloat16* vtl = (__nv_bfloat16*)VTlo;

    float o[8][4];
#pragma unroll
    for (int nj = 0; nj < 8; nj++)
#pragma unroll
        for (int c = 0; c < 4; c++) o[nj][c] = 0.f;
    float m0 = -INFINITY, m1 = -INFINITY;
    float l0 = 0.f, l1 = 0.f;

    const int qrow0 = qb + w * 16 + g;
    const int qrow1 = qrow0 + 8;
    const int qmax_w = qb + w * 16 + 15;
    const int kt_max = (qb + 127) >> 6;

    for (int kt = 0; kt <= kt_max; kt++) {
        const int k0 = kt * 64;
        __syncthreads();   // previous tile fully consumed
        // ---- load K tile (words) and V tile (transposed, per-element) ----
#pragma unroll
        for (int it = 0; it < 4; it++) {
            int idx = tid + it * 256;        // 0..1023
            int key = idx >> 4;
            int c4  = (idx & 15) * 4;
            const float* grow = base + (size_t)(k0 + key) * C3_ + h * HD_ + c4;
            float4 kv = *(const float4*)(grow + C_);
            float r0, r1, r2, r3;
            uint32_t h01 = pack_hi_pair(kv.x, kv.y, r0, r1);
            uint32_t h23 = pack_hi_pair(kv.z, kv.w, r2, r3);
            Khi[key * AT_STRIDE + c4 / 2]     = h01;
            Khi[key * AT_STRIDE + c4 / 2 + 1] = h23;
            Klo[key * AT_STRIDE + c4 / 2]     = pack_bf16x2(r0, r1);
            Klo[key * AT_STRIDE + c4 / 2 + 1] = pack_bf16x2(r2, r3);

            float4 vv = *(const float4*)(grow + 2 * C_);
            float vr[4] = {vv.x, vv.y, vv.z, vv.w};
#pragma unroll
            for (int j = 0; j < 4; j++) {
                __nv_bfloat16 hb = __float2bfloat16(vr[j]);
                vth[(c4 + j) * 72 + key] = hb;
                vtl[(c4 + j) * 72 + key] =
                    __float2bfloat16(vr[j] - __bfloat162float(hb));
            }
        }
        __syncthreads();

        if (k0 > qmax_w) continue;   // warp fully masked for this tile

        // ---- S = Q K^T (split 3-MMA) ----
        float s[8][4];
#pragma unroll
        for (int ni = 0; ni < 8; ni++) {
#pragma unroll
            for (int c = 0; c < 4; c++) s[ni][c] = 0.f;
            const int nrow = (8 * ni + g) * AT_STRIDE;
#pragma unroll
            for (int ks = 0; ks < 4; ks++) {
                uint32_t bhf[2], blf[2];
                bhf[0] = Khi[nrow + ks * 8 + q];
                bhf[1] = Khi[nrow + ks * 8 + q + 4];
                blf[0] = Klo[nrow + ks * 8 + q];
                blf[1] = Klo[nrow + ks * 8 + q + 4];
                mma_bf16(s[ni], qh[ks], bhf);
                mma_bf16(s[ni], qh[ks], blf);
                mma_bf16(s[ni], ql[ks], bhf);
            }
        }

        // ---- causal mask ----
        if (k0 + 63 > qb + w * 16) {
#pragma unroll
            for (int ni = 0; ni < 8; ni++) {
                int key = k0 + 8 * ni + 2 * q;
                s[ni][0] = (key     <= qrow0) ? s[ni][0] : -INFINITY;
                s[ni][1] = (key + 1 <= qrow0) ? s[ni][1] : -INFINITY;
                s[ni][2] = (key     <= qrow1) ? s[ni][2] : -INFINITY;
                s[ni][3] = (key + 1 <= qrow1) ? s[ni][3] : -INFINITY;
            }
        }

        // ---- online softmax (rows r0, r1) ----
        float mx0 = s[0][0], mx1 = s[0][2];
#pragma unroll
        for (int ni = 0; ni < 8; ni++) {
            mx0 = fmaxf(mx0, fmaxf(s[ni][0], s[ni][1]));
            mx1 = fmaxf(mx1, fmaxf(s[ni][2], s[ni][3]));
        }
        mx0 = fmaxf(mx0, __shfl_xor_sync(0xffffffff, mx0, 1));
        mx0 = fmaxf(mx0, __shfl_xor_sync(0xffffffff, mx0, 2));
        mx1 = fmaxf(mx1, __shfl_xor_sync(0xffffffff, mx1, 1));
        mx1 = fmaxf(mx1, __shfl_xor_sync(0xffffffff, mx1, 2));

        float mn0 = fmaxf(m0, mx0), mn1 = fmaxf(m1, mx1);
        float al0 = __expf(m0 - mn0), al1 = __expf(m1 - mn1);
        m0 = mn0; m1 = mn1;
        l0 *= al0; l1 *= al1;

        uint32_t phi[8][2], plo[8][2];
#pragma unroll
        for (int ni = 0; ni < 8; ni++) {
            float p0 = __expf(s[ni][0] - mn0);
            float p1 = __expf(s[ni][1] - mn0);
            float p2 = __expf(s[ni][2] - mn1);
            float p3 = __expf(s[ni][3] - mn1);
            l0 += p0 + p1;
            l1 += p2 + p3;
            float r0, r1, r2, r3;
            phi[ni][0] = pack_hi_pair(p0, p1, r0, r1);
            phi[ni][1] = pack_hi_pair(p2, p3, r2, r3);
            plo[ni][0] = pack_bf16x2(r0, r1);
            plo[ni][1] = pack_bf16x2(r2, r3);
            // rescale O for this tile
            o[ni][0] *= al0; o[ni][1] *= al0;
            o[ni][2] *= al1; o[ni][3] *= al1;
        }

        // ---- O += P V (split 3-MMA) ----
#pragma unroll
        for (int nj = 0; nj < 8; nj++) {
            const int nrow = (8 * nj + g) * AT_STRIDE;
#pragma unroll
            for (int ks = 0; ks < 4; ks++) {
                uint32_t af_hi[4] = {phi[2*ks][0], phi[2*ks][1],
                                     phi[2*ks+1][0], phi[2*ks+1][1]};
                uint32_t af_lo[4] = {plo[2*ks][0], plo[2*ks][1],
                                     plo[2*ks+1][0], plo[2*ks+1][1]};
                uint32_t bhf[2], blf[2];
                bhf[0] = VThi[nrow + ks * 8 + q];
                bhf[1] = VThi[nrow + ks * 8 + q + 4];
                blf[0] = VTlo[nrow + ks * 8 + q];
                blf[1] = VTlo[nrow + ks * 8 + q + 4];
                mma_bf16(o[nj], af_hi, bhf);
                mma_bf16(o[nj], af_hi, blf);
                mma_bf16(o[nj], af_lo, bhf);
            }
        }
    }

    // ---- epilogue ----
    l0 += __shfl_xor_sync(0xffffffff, l0, 1);
    l0 += __shfl_xor_sync(0xffffffff, l0, 2);
    l1 += __shfl_xor_sync(0xffffffff, l1, 1);
    l1 += __shfl_xor_sync(0xffffffff, l1, 2);
    const float inv0 = 1.f / l0;
    const float inv1 = 1.f / l1;

    float* y0 = y + (size_t)(b * T_ + qrow0) * C_ + h * HD_;
    float* y1 = y + (size_t)(b * T_ + qrow1) * C_ + h * HD_;
#pragma unroll
    for (int nj = 0; nj < 8; nj++) {
        int c = 8 * nj + 2 * q;
        *(float2*)(y0 + c) = make_float2(o[nj][0] * inv0, o[nj][1] * inv0);
        *(float2*)(y1 + c) = make_float2(o[nj][2] * inv1, o[nj][3] * inv1);
    }
}

// ---------------- launch ----------------
extern "C" void kernel_launch(void* const* d_in, const int* in_sizes, int n_in,
                              void* d_out, int out_size)
{
    const float* x     = (const float*)d_in[0];
    const float* w_qkv = (const float*)d_in[1];
    const float* b_qkv = (const float*)d_in[2];
    const float* w_out = (const float*)d_in[3];
    const float* b_out = (const float*)d_in[4];
    float* out = (float*)d_out;

    float* qkv_ptr; float* y_ptr;
    __nv_bfloat16 *xhi, *xlo, *yhi, *ylo, *wqhi, *wqlo, *wohi, *wolo;
    cudaGetSymbolAddress((void**)&qkv_ptr, g_qkv);
    cudaGetSymbolAddress((void**)&y_ptr,   g_y);
    cudaGetSymbolAddress((void**)&xhi, g_x_hi);
    cudaGetSymbolAddress((void**)&xlo, g_x_lo);
    cudaGetSymbolAddress((void**)&yhi, g_y_hi);
    cudaGetSymbolAddress((void**)&ylo, g_y_lo);
    cudaGetSymbolAddress((void**)&wqhi, g_wqkvT_hi);
    cudaGetSymbolAddress((void**)&wqlo, g_wqkvT_lo);
    cudaGetSymbolAddress((void**)&wohi, g_woutT_hi);
    cudaGetSymbolAddress((void**)&wolo, g_woutT_lo);

    static bool smem_set = false;
    if (!smem_set) {
        cudaFuncSetAttribute(gemm_bf16x2_kernel,
                             cudaFuncAttributeMaxDynamicSharedMemorySize,
                             8 * TILE_WORDS * 4);
        smem_set = true;
    }
    const int gemm_smem = 8 * TILE_WORDS * 4;   // 81920 B

    split_f32_kernel<<<1024, 256>>>(x, xhi, xlo, M_ * C_);
    {
        dim3 grid(C3_ / 32, C_ / 32), blk(32, 8);
        split_transpose_kernel<<<grid, blk>>>(w_qkv, wqhi, wqlo, C_, C3_);
    }
    {
        dim3 grid(C_ / 32, C_ / 32), blk(32, 8);
        split_transpose_kernel<<<grid, blk>>>(w_out, wohi, wolo, C_, C_);
    }

    // 1) qkv = x @ w_qkv + b_qkv
    {
        dim3 grid(C3_ / GBN, M_ / GBM);
        gemm_bf16x2_kernel<<<grid, 256, gemm_smem>>>(
            xhi, xlo, wqhi, wqlo, b_qkv, qkv_ptr, M_, C3_, C_);
    }

    // 2) causal attention (tensor cores)
    {
        dim3 grid(B_ * H_, T_ / 128);
        attn_mma_kernel<<<grid, 256>>>(qkv_ptr, y_ptr);
    }

    split_f32_kernel<<<1024, 256>>>(y_ptr, yhi, ylo, M_ * C_);

    // 3) out = y @ w_out + b_out
    {
        dim3 grid(C_ / GBN, M_ / GBM);
        gemm_bf16x2_kernel<<<grid, 256, gemm_smem>>>(
            yhi, ylo, wohi, wolo, b_out, out, M_, C_, C_);
    }
}

// round 6
// speedup vs baseline: 2.5738x; 1.0956x over previous
#include <cuda_runtime.h>
#include <cuda_bf16.h>
#include <math.h>
#include <stdint.h>

// Problem dims (fixed by the dataset)
#define B_   2
#define T_   2048
#define C_   1024
#define H_   16
#define HD_  64
#define C3_  (3*C_)
#define M_   (B_*T_)          // 4096 rows

// ---------------- scratch (no cudaMalloc allowed) ----------------
__device__ float g_qkv[(size_t)M_ * C3_];         // [B*T, 3C]
__device__ __nv_bfloat16 g_x_hi[(size_t)M_ * C_];
__device__ __nv_bfloat16 g_x_lo[(size_t)M_ * C_];
__device__ __nv_bfloat16 g_y_hi[(size_t)M_ * C_];
__device__ __nv_bfloat16 g_y_lo[(size_t)M_ * C_];
__device__ __nv_bfloat16 g_wqkvT_hi[(size_t)C3_ * C_];  // [N=3C][K=C]
__device__ __nv_bfloat16 g_wqkvT_lo[(size_t)C3_ * C_];
__device__ __nv_bfloat16 g_woutT_hi[(size_t)C_ * C_];   // [N=C][K=C]
__device__ __nv_bfloat16 g_woutT_lo[(size_t)C_ * C_];

// ---------------- helpers ----------------
__device__ __forceinline__ uint32_t smem_u32(const void* p) {
    return (uint32_t)__cvta_generic_to_shared(p);
}
__device__ __forceinline__ void cp_async16(void* s, const void* g) {
    asm volatile("cp.async.cg.shared.global [%0], [%1], 16;\n"
                 :: "r"(smem_u32(s)), "l"(g));
}
__device__ __forceinline__ void cp_commit() {
    asm volatile("cp.async.commit_group;\n" ::);
}
__device__ __forceinline__ void cp_wait0() {
    asm volatile("cp.async.wait_group 0;\n" ::);
}
__device__ __forceinline__ void mma_bf16(float* d, const uint32_t* a, const uint32_t* b) {
    asm volatile(
        "mma.sync.aligned.m16n8k16.row.col.f32.bf16.bf16.f32 "
        "{%0,%1,%2,%3}, {%4,%5,%6,%7}, {%8,%9}, {%0,%1,%2,%3};\n"
        : "+f"(d[0]), "+f"(d[1]), "+f"(d[2]), "+f"(d[3])
        : "r"(a[0]), "r"(a[1]), "r"(a[2]), "r"(a[3]),
          "r"(b[0]), "r"(b[1]));
}
__device__ __forceinline__ void ldsm_x4(uint32_t* r, uint32_t addr) {
    asm volatile("ldmatrix.sync.aligned.m8n8.x4.shared.b16 {%0,%1,%2,%3}, [%4];"
                 : "=r"(r[0]), "=r"(r[1]), "=r"(r[2]), "=r"(r[3])
                 : "r"(addr));
}
__device__ __forceinline__ uint32_t pack_bf16x2(float lo, float hi) {
    uint32_t r;
    asm("cvt.rn.bf16x2.f32 %0, %1, %2;" : "=r"(r) : "f"(hi), "f"(lo));
    return r;
}
__device__ __forceinline__ uint32_t pack_hi_pair(float a, float b,
                                                 float& ra, float& rb) {
    uint32_t w = pack_bf16x2(a, b);
    __nv_bfloat162 h = *reinterpret_cast<__nv_bfloat162*>(&w);
    ra = a - __bfloat162float(h.x);
    rb = b - __bfloat162float(h.y);
    return w;
}

// ---------------- prep kernels ----------------
__global__ void split_f32_kernel(const float* __restrict__ src,
                                 __nv_bfloat16* __restrict__ hi,
                                 __nv_bfloat16* __restrict__ lo, int n)
{
    int i = blockIdx.x * blockDim.x + threadIdx.x;
    int stride = gridDim.x * blockDim.x;
    for (; i < n; i += stride) {
        float v = src[i];
        __nv_bfloat16 h = __float2bfloat16(v);
        hi[i] = h;
        lo[i] = __float2bfloat16(v - __bfloat162float(h));
    }
}

__global__ void split_transpose_kernel(const float* __restrict__ src,
                                       __nv_bfloat16* __restrict__ hi,
                                       __nv_bfloat16* __restrict__ lo,
                                       int K, int N)
{
    __shared__ float ts[32][33];
    const int n0 = blockIdx.x * 32;
    const int k0 = blockIdx.y * 32;
    const int tx = threadIdx.x;
    const int ty = threadIdx.y;
#pragma unroll
    for (int i = 0; i < 4; i++) {
        int k = k0 + ty + i * 8;
        ts[ty + i * 8][tx] = src[(size_t)k * N + n0 + tx];
    }
    __syncthreads();
#pragma unroll
    for (int i = 0; i < 4; i++) {
        int n = n0 + ty + i * 8;
        float v = ts[tx][ty + i * 8];
        __nv_bfloat16 h = __float2bfloat16(v);
        size_t idx = (size_t)n * K + k0 + tx;
        hi[idx] = h;
        lo[idx] = __float2bfloat16(v - __bfloat162float(h));
    }
}

// ================= bf16 split-2 tensor-core GEMM (ldmatrix) =================
// C = A[M,K] @ W[K,N] + bias; A = (Ahi+Alo) bf16 [M][K], W = (Bhi+Blo) [N][K].
// D += Ahi*Bhi + Ahi*Blo + Alo*Bhi.
// Tiles: BM=128, BN=128, BK=32. 256 threads = 8 warps (2x4), warp tile 64x32.
#define GBM 128
#define GBN 128
#define GBK 32
#define TSTRIDE 20                     // uint32 words per SMEM tile row (80 B)
#define TILE_WORDS (128 * TSTRIDE)

__global__ __launch_bounds__(256, 2) void gemm_bf16x2_kernel(
    const __nv_bfloat16* __restrict__ Ahi, const __nv_bfloat16* __restrict__ Alo,
    const __nv_bfloat16* __restrict__ Bhi, const __nv_bfloat16* __restrict__ Blo,
    const float* __restrict__ bias, float* __restrict__ Cout,
    int M, int N, int K)
{
    extern __shared__ uint32_t sm[];
    uint32_t* tiles[2][4];   // 0=Ahi 1=Alo 2=Bhi 3=Blo
#pragma unroll
    for (int b = 0; b < 2; b++)
#pragma unroll
        for (int t = 0; t < 4; t++)
            tiles[b][t] = sm + (b * 4 + t) * TILE_WORDS;

    const int tid  = threadIdx.x;
    const int wid  = tid >> 5;
    const int lane = tid & 31;
    const int g    = lane >> 2;
    const int q    = lane & 3;
    const int row0 = blockIdx.y * GBM;
    const int col0 = blockIdx.x * GBN;
    const int wm   = (wid & 1) * 64;
    const int wn   = (wid >> 1) * 32;

    // ---- per-lane ldmatrix relative byte offsets (within a tile) ----
    const int grp = lane >> 3;        // 0..3 (which 8x8 matrix)
    const int rl  = lane & 7;         // row within matrix
    // A: m0..m3 = (r0-7,k0-7),(r8-15,k0-7),(r0-7,k8-15),(r8-15,k8-15)
    uint32_t aRel[4];
#pragma unroll
    for (int mi = 0; mi < 4; mi++)
        aRel[mi] = (uint32_t)((wm + mi * 16 + (grp & 1) * 8 + rl) * 80
                              + (grp >> 1) * 16);
    // B: m0..m3 = (n0-7,k0-7),(n0-7,k8-15),(n8-15,k0-7),(n8-15,k8-15)
    uint32_t bRel[2];
#pragma unroll
    for (int ni2 = 0; ni2 < 2; ni2++)
        bRel[ni2] = (uint32_t)((wn + ni2 * 16 + (grp >> 1) * 8 + rl) * 80
                               + (grp & 1) * 16);

    float acc[4][4][4];
#pragma unroll
    for (int mi = 0; mi < 4; mi++)
#pragma unroll
        for (int ni = 0; ni < 4; ni++)
#pragma unroll
            for (int r = 0; r < 4; r++) acc[mi][ni][r] = 0.f;

    const __nv_bfloat16* srcs[4] = {Ahi, Alo, Bhi, Blo};
    auto load_tile = [&](int kt, int buf) {
        const int k0 = kt * GBK;
#pragma unroll
        for (int t = 0; t < 4; t++) {
            const __nv_bfloat16* base = srcs[t] +
                (size_t)((t < 2) ? row0 : col0) * K + k0;
#pragma unroll
            for (int it = 0; it < 2; it++) {
                int idx = tid + it * 256;
                int r   = idx >> 2;
                int f   = idx & 3;
                cp_async16(&tiles[buf][t][r * TSTRIDE + f * 4],
                           base + (size_t)r * K + f * 8);
            }
        }
        cp_commit();
    };

    load_tile(0, 0);
    cp_wait0();
    __syncthreads();

    const int KT = K / GBK;
    for (int kt = 0; kt < KT; kt++) {
        const int buf = kt & 1;
        if (kt + 1 < KT) load_tile(kt + 1, buf ^ 1);

        const uint32_t baseAh = smem_u32(tiles[buf][0]);
        const uint32_t baseAl = smem_u32(tiles[buf][1]);
        const uint32_t baseBh = smem_u32(tiles[buf][2]);
        const uint32_t baseBl = smem_u32(tiles[buf][3]);

#pragma unroll
        for (int ks = 0; ks < 2; ks++) {
            const uint32_t ko = (uint32_t)ks * 32;   // k16 step = 32 bytes
            uint32_t ah[4][4], al[4][4], bh[4][2], bl[4][2];
#pragma unroll
            for (int mi = 0; mi < 4; mi++) {
                ldsm_x4(ah[mi], baseAh + aRel[mi] + ko);
                ldsm_x4(al[mi], baseAl + aRel[mi] + ko);
            }
#pragma unroll
            for (int ni2 = 0; ni2 < 2; ni2++) {
                uint32_t t4[4];
                ldsm_x4(t4, baseBh + bRel[ni2] + ko);
                bh[2*ni2][0] = t4[0]; bh[2*ni2][1] = t4[1];
                bh[2*ni2+1][0] = t4[2]; bh[2*ni2+1][1] = t4[3];
                ldsm_x4(t4, baseBl + bRel[ni2] + ko);
                bl[2*ni2][0] = t4[0]; bl[2*ni2][1] = t4[1];
                bl[2*ni2+1][0] = t4[2]; bl[2*ni2+1][1] = t4[3];
            }
#pragma unroll
            for (int mi = 0; mi < 4; mi++)
#pragma unroll
                for (int ni = 0; ni < 4; ni++) {
                    mma_bf16(acc[mi][ni], ah[mi], bh[ni]);
                    mma_bf16(acc[mi][ni], ah[mi], bl[ni]);
                    mma_bf16(acc[mi][ni], al[mi], bh[ni]);
                }
        }

        if (kt + 1 < KT) cp_wait0();
        __syncthreads();
    }

#pragma unroll
    for (int mi = 0; mi < 4; mi++) {
#pragma unroll
        for (int ni = 0; ni < 4; ni++) {
            int r = row0 + wm + mi * 16 + g;
            int c = col0 + wn + ni * 8 + 2 * q;
            float b0 = bias[c], b1 = bias[c + 1];
            float2 v0 = make_float2(acc[mi][ni][0] + b0, acc[mi][ni][1] + b1);
            float2 v1 = make_float2(acc[mi][ni][2] + b0, acc[mi][ni][3] + b1);
            *(float2*)(Cout + (size_t)r * N + c)       = v0;
            *(float2*)(Cout + (size_t)(r + 8) * N + c) = v1;
        }
    }
}

// ================= MMA flash attention (bf16 split, fp32 softmax) =================
// Block: 256 threads = 8 warps, 128 queries of one (b,h). K/V tiles of 64 keys.
#define AT_STRIDE 36

__global__ __launch_bounds__(256) void attn_mma_kernel(
    const float* __restrict__ qkv,
    __nv_bfloat16* __restrict__ yhi, __nv_bfloat16* __restrict__ ylo)
{
    __shared__ uint32_t sm[9216];

    const int tid  = threadIdx.x;
    const int w    = tid >> 5;
    const int lane = tid & 31;
    const int g    = lane >> 2;
    const int q    = lane & 3;
    const int bh   = blockIdx.x;
    const int b    = bh >> 4;
    const int h    = bh & 15;
    const int qt   = (gridDim.y - 1) - blockIdx.y;   // heavy blocks first
    const int qb   = qt * 128;

    const float* base = qkv + (size_t)b * T_ * C3_;

#pragma unroll
    for (int it = 0; it < 8; it++) {
        int idx = tid + it * 256;
        int row = idx >> 4;
        int c4  = (idx & 15) * 4;
        float4 v = *(const float4*)(base + (size_t)(qb + row) * C3_ + h * HD_ + c4);
        float r0, r1, r2, r3;
        uint32_t h01 = pack_hi_pair(v.x * 0.125f, v.y * 0.125f, r0, r1);
        uint32_t h23 = pack_hi_pair(v.z * 0.125f, v.w * 0.125f, r2, r3);
        sm[row * AT_STRIDE + c4 / 2]     = h01;
        sm[row * AT_STRIDE + c4 / 2 + 1] = h23;
        sm[4608 + row * AT_STRIDE + c4 / 2]     = pack_bf16x2(r0, r1);
        sm[4608 + row * AT_STRIDE + c4 / 2 + 1] = pack_bf16x2(r2, r3);
    }
    __syncthreads();

    uint32_t qh[4][4], ql[4][4];
    {
        const int r0 = w * 16 + g;
        const int r1 = r0 + 8;
#pragma unroll
        for (int ks = 0; ks < 4; ks++) {
            int o0 = r0 * AT_STRIDE + ks * 8 + q;
            int o1 = r1 * AT_STRIDE + ks * 8 + q;
            qh[ks][0] = sm[o0];     qh[ks][1] = sm[o1];
            qh[ks][2] = sm[o0 + 4]; qh[ks][3] = sm[o1 + 4];
            ql[ks][0] = sm[4608 + o0];     ql[ks][1] = sm[4608 + o1];
            ql[ks][2] = sm[4608 + o0 + 4]; ql[ks][3] = sm[4608 + o1 + 4];
        }
    }

    uint32_t* Khi  = sm;
    uint32_t* Klo  = sm + 2304;
    uint32_t* VThi = sm + 4608;
    uint32_t* VTlo = sm + 6912;
    __nv_bfloat16* vth = (__nv_bfloat16*)VThi;
    __nv_bfloat16* vtl = (__nv_bfloat16*)VTlo;

    float o[8][4];
#pragma unroll
    for (int nj = 0; nj < 8; nj++)
#pragma unroll
        for (int c = 0; c < 4; c++) o[nj][c] = 0.f;
    float m0 = -INFINITY, m1 = -INFINITY;
    float l0 = 0.f, l1 = 0.f;

    const int qrow0 = qb + w * 16 + g;
    const int qrow1 = qrow0 + 8;
    const int qmax_w = qb + w * 16 + 15;
    const int kt_max = (qb + 127) >> 6;

    for (int kt = 0; kt <= kt_max; kt++) {
        const int k0 = kt * 64;
        __syncthreads();
#pragma unroll
        for (int it = 0; it < 4; it++) {
            int idx = tid + it * 256;
            int key = idx >> 4;
            int c4  = (idx & 15) * 4;
            const float* grow = base + (size_t)(k0 + key) * C3_ + h * HD_ + c4;
            float4 kv = *(const float4*)(grow + C_);
            float r0, r1, r2, r3;
            uint32_t h01 = pack_hi_pair(kv.x, kv.y, r0, r1);
            uint32_t h23 = pack_hi_pair(kv.z, kv.w, r2, r3);
            Khi[key * AT_STRIDE + c4 / 2]     = h01;
            Khi[key * AT_STRIDE + c4 / 2 + 1] = h23;
            Klo[key * AT_STRIDE + c4 / 2]     = pack_bf16x2(r0, r1);
            Klo[key * AT_STRIDE + c4 / 2 + 1] = pack_bf16x2(r2, r3);

            float4 vv = *(const float4*)(grow + 2 * C_);
            float vr[4] = {vv.x, vv.y, vv.z, vv.w};
#pragma unroll
            for (int j = 0; j < 4; j++) {
                __nv_bfloat16 hb = __float2bfloat16(vr[j]);
                vth[(c4 + j) * 72 + key] = hb;
                vtl[(c4 + j) * 72 + key] =
                    __float2bfloat16(vr[j] - __bfloat162float(hb));
            }
        }
        __syncthreads();

        if (k0 > qmax_w) continue;

        float s[8][4];
#pragma unroll
        for (int ni = 0; ni < 8; ni++) {
#pragma unroll
            for (int c = 0; c < 4; c++) s[ni][c] = 0.f;
            const int nrow = (8 * ni + g) * AT_STRIDE;
#pragma unroll
            for (int ks = 0; ks < 4; ks++) {
                uint32_t bhf[2], blf[2];
                bhf[0] = Khi[nrow + ks * 8 + q];
                bhf[1] = Khi[nrow + ks * 8 + q + 4];
                blf[0] = Klo[nrow + ks * 8 + q];
                blf[1] = Klo[nrow + ks * 8 + q + 4];
                mma_bf16(s[ni], qh[ks], bhf);
                mma_bf16(s[ni], qh[ks], blf);
                mma_bf16(s[ni], ql[ks], bhf);
            }
        }

        if (k0 + 63 > qb + w * 16) {
#pragma unroll
            for (int ni = 0; ni < 8; ni++) {
                int key = k0 + 8 * ni + 2 * q;
                s[ni][0] = (key     <= qrow0) ? s[ni][0] : -INFINITY;
                s[ni][1] = (key + 1 <= qrow0) ? s[ni][1] : -INFINITY;
                s[ni][2] = (key     <= qrow1) ? s[ni][2] : -INFINITY;
                s[ni][3] = (key + 1 <= qrow1) ? s[ni][3] : -INFINITY;
            }
        }

        float mx0 = s[0][0], mx1 = s[0][2];
#pragma unroll
        for (int ni = 0; ni < 8; ni++) {
            mx0 = fmaxf(mx0, fmaxf(s[ni][0], s[ni][1]));
            mx1 = fmaxf(mx1, fmaxf(s[ni][2], s[ni][3]));
        }
        mx0 = fmaxf(mx0, __shfl_xor_sync(0xffffffff, mx0, 1));
        mx0 = fmaxf(mx0, __shfl_xor_sync(0xffffffff, mx0, 2));
        mx1 = fmaxf(mx1, __shfl_xor_sync(0xffffffff, mx1, 1));
        mx1 = fmaxf(mx1, __shfl_xor_sync(0xffffffff, mx1, 2));

        float mn0 = fmaxf(m0, mx0), mn1 = fmaxf(m1, mx1);
        float al0 = __expf(m0 - mn0), al1 = __expf(m1 - mn1);
        m0 = mn0; m1 = mn1;
        l0 *= al0; l1 *= al1;

        uint32_t phi[8][2], plo[8][2];
#pragma unroll
        for (int ni = 0; ni < 8; ni++) {
            float p0 = __expf(s[ni][0] - mn0);
            float p1 = __expf(s[ni][1] - mn0);
            float p2 = __expf(s[ni][2] - mn1);
            float p3 = __expf(s[ni][3] - mn1);
            l0 += p0 + p1;
            l1 += p2 + p3;
            float r0, r1, r2, r3;
            phi[ni][0] = pack_hi_pair(p0, p1, r0, r1);
            phi[ni][1] = pack_hi_pair(p2, p3, r2, r3);
            plo[ni][0] = pack_bf16x2(r0, r1);
            plo[ni][1] = pack_bf16x2(r2, r3);
            o[ni][0] *= al0; o[ni][1] *= al0;
            o[ni][2] *= al1; o[ni][3] *= al1;
        }

#pragma unroll
        for (int nj = 0; nj < 8; nj++) {
            const int nrow = (8 * nj + g) * AT_STRIDE;
#pragma unroll
            for (int ks = 0; ks < 4; ks++) {
                uint32_t af_hi[4] = {phi[2*ks][0], phi[2*ks][1],
                                     phi[2*ks+1][0], phi[2*ks+1][1]};
                uint32_t af_lo[4] = {plo[2*ks][0], plo[2*ks][1],
                                     plo[2*ks+1][0], plo[2*ks+1][1]};
                uint32_t bhf[2], blf[2];
                bhf[0] = VThi[nrow + ks * 8 + q];
                bhf[1] = VThi[nrow + ks * 8 + q + 4];
                blf[0] = VTlo[nrow + ks * 8 + q];
                blf[1] = VTlo[nrow + ks * 8 + q + 4];
                mma_bf16(o[nj], af_hi, bhf);
                mma_bf16(o[nj], af_hi, blf);
                mma_bf16(o[nj], af_lo, bhf);
            }
        }
    }

    l0 += __shfl_xor_sync(0xffffffff, l0, 1);
    l0 += __shfl_xor_sync(0xffffffff, l0, 2);
    l1 += __shfl_xor_sync(0xffffffff, l1, 1);
    l1 += __shfl_xor_sync(0xffffffff, l1, 2);
    const float inv0 = 1.f / l0;
    const float inv1 = 1.f / l1;

    // write y directly as hi/lo bf16 (feeds out-proj GEMM; no split pass)
    __nv_bfloat16* yh0 = yhi + (size_t)(b * T_ + qrow0) * C_ + h * HD_;
    __nv_bfloat16* yl0 = ylo + (size_t)(b * T_ + qrow0) * C_ + h * HD_;
    __nv_bfloat16* yh1 = yhi + (size_t)(b * T_ + qrow1) * C_ + h * HD_;
    __nv_bfloat16* yl1 = ylo + (size_t)(b * T_ + qrow1) * C_ + h * HD_;
#pragma unroll
    for (int nj = 0; nj < 8; nj++) {
        int c = 8 * nj + 2 * q;
        float a0 = o[nj][0] * inv0, a1 = o[nj][1] * inv0;
        float a2 = o[nj][2] * inv1, a3 = o[nj][3] * inv1;
        float r0, r1, r2, r3;
        uint32_t h01 = pack_hi_pair(a0, a1, r0, r1);
        uint32_t h23 = pack_hi_pair(a2, a3, r2, r3);
        *(uint32_t*)(yh0 + c) = h01;
        *(uint32_t*)(yl0 + c) = pack_bf16x2(r0, r1);
        *(uint32_t*)(yh1 + c) = h23;
        *(uint32_t*)(yl1 + c) = pack_bf16x2(r2, r3);
    }
}

// ---------------- launch ----------------
extern "C" void kernel_launch(void* const* d_in, const int* in_sizes, int n_in,
                              void* d_out, int out_size)
{
    const float* x     = (const float*)d_in[0];
    const float* w_qkv = (const float*)d_in[1];
    const float* b_qkv = (const float*)d_in[2];
    const float* w_out = (const float*)d_in[3];
    const float* b_out = (const float*)d_in[4];
    float* out = (float*)d_out;

    float* qkv_ptr;
    __nv_bfloat16 *xhi, *xlo, *yhi, *ylo, *wqhi, *wqlo, *wohi, *wolo;
    cudaGetSymbolAddress((void**)&qkv_ptr, g_qkv);
    cudaGetSymbolAddress((void**)&xhi, g_x_hi);
    cudaGetSymbolAddress((void**)&xlo, g_x_lo);
    cudaGetSymbolAddress((void**)&yhi, g_y_hi);
    cudaGetSymbolAddress((void**)&ylo, g_y_lo);
    cudaGetSymbolAddress((void**)&wqhi, g_wqkvT_hi);
    cudaGetSymbolAddress((void**)&wqlo, g_wqkvT_lo);
    cudaGetSymbolAddress((void**)&wohi, g_woutT_hi);
    cudaGetSymbolAddress((void**)&wolo, g_woutT_lo);

    static bool smem_set = false;
    if (!smem_set) {
        cudaFuncSetAttribute(gemm_bf16x2_kernel,
                             cudaFuncAttributeMaxDynamicSharedMemorySize,
                             8 * TILE_WORDS * 4);
        smem_set = true;
    }
    const int gemm_smem = 8 * TILE_WORDS * 4;   // 81920 B

    split_f32_kernel<<<1024, 256>>>(x, xhi, xlo, M_ * C_);
    {
        dim3 grid(C3_ / 32, C_ / 32), blk(32, 8);
        split_transpose_kernel<<<grid, blk>>>(w_qkv, wqhi, wqlo, C_, C3_);
    }
    {
        dim3 grid(C_ / 32, C_ / 32), blk(32, 8);
        split_transpose_kernel<<<grid, blk>>>(w_out, wohi, wolo, C_, C_);
    }

    // 1) qkv = x @ w_qkv + b_qkv
    {
        dim3 grid(C3_ / GBN, M_ / GBM);
        gemm_bf16x2_kernel<<<grid, 256, gemm_smem>>>(
            xhi, xlo, wqhi, wqlo, b_qkv, qkv_ptr, M_, C3_, C_);
    }

    // 2) causal attention -> y (hi/lo bf16 written directly)
    {
        dim3 grid(B_ * H_, T_ / 128);
        attn_mma_kernel<<<grid, 256>>>(qkv_ptr, yhi, ylo);
    }

    // 3) out = y @ w_out + b_out
    {
        dim3 grid(C_ / GBN, M_ / GBM);
        gemm_bf16x2_kernel<<<grid, 256, gemm_smem>>>(
            yhi, ylo, wohi, wolo, b_out, out, M_, C_, C_);
    }
}

// round 7
// speedup vs baseline: 2.9901x; 1.1617x over previous
#include <cuda_runtime.h>
#include <cuda_bf16.h>
#include <math.h>
#include <stdint.h>

// Problem dims (fixed by the dataset)
#define B_   2
#define T_   2048
#define C_   1024
#define H_   16
#define HD_  64
#define C3_  (3*C_)
#define M_   (B_*T_)          // 4096 rows

// ---------------- scratch (no cudaMalloc allowed) ----------------
__device__ __nv_bfloat16 g_qkv_hi[(size_t)M_ * C3_];
__device__ __nv_bfloat16 g_qkv_lo[(size_t)M_ * C3_];
__device__ __nv_bfloat16 g_x_hi[(size_t)M_ * C_];
__device__ __nv_bfloat16 g_x_lo[(size_t)M_ * C_];
__device__ __nv_bfloat16 g_y_hi[(size_t)M_ * C_];
__device__ __nv_bfloat16 g_y_lo[(size_t)M_ * C_];
__device__ __nv_bfloat16 g_wqkvT_hi[(size_t)C3_ * C_];  // [N=3C][K=C]
__device__ __nv_bfloat16 g_wqkvT_lo[(size_t)C3_ * C_];
__device__ __nv_bfloat16 g_woutT_hi[(size_t)C_ * C_];   // [N=C][K=C]
__device__ __nv_bfloat16 g_woutT_lo[(size_t)C_ * C_];

// ---------------- helpers ----------------
__device__ __forceinline__ uint32_t smem_u32(const void* p) {
    return (uint32_t)__cvta_generic_to_shared(p);
}
__device__ __forceinline__ void cp_async16(void* s, const void* g) {
    asm volatile("cp.async.cg.shared.global [%0], [%1], 16;\n"
                 :: "r"(smem_u32(s)), "l"(g));
}
__device__ __forceinline__ void cp_commit() {
    asm volatile("cp.async.commit_group;\n" ::);
}
__device__ __forceinline__ void cp_wait0() {
    asm volatile("cp.async.wait_group 0;\n" ::);
}
__device__ __forceinline__ void mma_bf16(float* d, const uint32_t* a, const uint32_t* b) {
    asm volatile(
        "mma.sync.aligned.m16n8k16.row.col.f32.bf16.bf16.f32 "
        "{%0,%1,%2,%3}, {%4,%5,%6,%7}, {%8,%9}, {%0,%1,%2,%3};\n"
        : "+f"(d[0]), "+f"(d[1]), "+f"(d[2]), "+f"(d[3])
        : "r"(a[0]), "r"(a[1]), "r"(a[2]), "r"(a[3]),
          "r"(b[0]), "r"(b[1]));
}
__device__ __forceinline__ void ldsm_x4(uint32_t* r, uint32_t addr) {
    asm volatile("ldmatrix.sync.aligned.m8n8.x4.shared.b16 {%0,%1,%2,%3}, [%4];"
                 : "=r"(r[0]), "=r"(r[1]), "=r"(r[2]), "=r"(r[3])
                 : "r"(addr));
}
__device__ __forceinline__ void ldsm_x4_trans(uint32_t* r, uint32_t addr) {
    asm volatile("ldmatrix.sync.aligned.m8n8.x4.trans.shared.b16 {%0,%1,%2,%3}, [%4];"
                 : "=r"(r[0]), "=r"(r[1]), "=r"(r[2]), "=r"(r[3])
                 : "r"(addr));
}
__device__ __forceinline__ uint32_t pack_bf16x2(float lo, float hi) {
    uint32_t r;
    asm("cvt.rn.bf16x2.f32 %0, %1, %2;" : "=r"(r) : "f"(hi), "f"(lo));
    return r;
}
__device__ __forceinline__ uint32_t pack_hi_pair(float a, float b,
                                                 float& ra, float& rb) {
    uint32_t w = pack_bf16x2(a, b);
    __nv_bfloat162 h = *reinterpret_cast<__nv_bfloat162*>(&w);
    ra = a - __bfloat162float(h.x);
    rb = b - __bfloat162float(h.y);
    return w;
}

// ---------------- prep kernels ----------------
__global__ void split_f32_kernel(const float* __restrict__ src,
                                 __nv_bfloat16* __restrict__ hi,
                                 __nv_bfloat16* __restrict__ lo, int n)
{
    int i = blockIdx.x * blockDim.x + threadIdx.x;
    int stride = gridDim.x * blockDim.x;
    for (; i < n; i += stride) {
        float v = src[i];
        __nv_bfloat16 h = __float2bfloat16(v);
        hi[i] = h;
        lo[i] = __float2bfloat16(v - __bfloat162float(h));
    }
}

__global__ void split_transpose_kernel(const float* __restrict__ src,
                                       __nv_bfloat16* __restrict__ hi,
                                       __nv_bfloat16* __restrict__ lo,
                                       int K, int N)
{
    __shared__ float ts[32][33];
    const int n0 = blockIdx.x * 32;
    const int k0 = blockIdx.y * 32;
    const int tx = threadIdx.x;
    const int ty = threadIdx.y;
#pragma unroll
    for (int i = 0; i < 4; i++) {
        int k = k0 + ty + i * 8;
        ts[ty + i * 8][tx] = src[(size_t)k * N + n0 + tx];
    }
    __syncthreads();
#pragma unroll
    for (int i = 0; i < 4; i++) {
        int n = n0 + ty + i * 8;
        float v = ts[tx][ty + i * 8];
        __nv_bfloat16 h = __float2bfloat16(v);
        size_t idx = (size_t)n * K + k0 + tx;
        hi[idx] = h;
        lo[idx] = __float2bfloat16(v - __bfloat162float(h));
    }
}

// ================= bf16 split-2 tensor-core GEMM (ldmatrix) =================
#define GBM 128
#define GBN 128
#define GBK 32
#define TSTRIDE 20                     // uint32 words per SMEM tile row (80 B)
#define TILE_WORDS (128 * TSTRIDE)

__global__ __launch_bounds__(256, 2) void gemm_bf16x2_kernel(
    const __nv_bfloat16* __restrict__ Ahi, const __nv_bfloat16* __restrict__ Alo,
    const __nv_bfloat16* __restrict__ Bhi, const __nv_bfloat16* __restrict__ Blo,
    const float* __restrict__ bias,
    float* __restrict__ Cout,                     // fp32 path (if Chi==nullptr)
    __nv_bfloat16* __restrict__ Chi,              // hi/lo path
    __nv_bfloat16* __restrict__ Clo,
    int M, int N, int K)
{
    extern __shared__ uint32_t sm[];
    uint32_t* tiles[2][4];   // 0=Ahi 1=Alo 2=Bhi 3=Blo
#pragma unroll
    for (int b = 0; b < 2; b++)
#pragma unroll
        for (int t = 0; t < 4; t++)
            tiles[b][t] = sm + (b * 4 + t) * TILE_WORDS;

    const int tid  = threadIdx.x;
    const int wid  = tid >> 5;
    const int lane = tid & 31;
    const int g    = lane >> 2;
    const int q    = lane & 3;
    const int row0 = blockIdx.y * GBM;
    const int col0 = blockIdx.x * GBN;
    const int wm   = (wid & 1) * 64;
    const int wn   = (wid >> 1) * 32;

    const int grp = lane >> 3;
    const int rl  = lane & 7;
    uint32_t aRel[4];
#pragma unroll
    for (int mi = 0; mi < 4; mi++)
        aRel[mi] = (uint32_t)((wm + mi * 16 + (grp & 1) * 8 + rl) * 80
                              + (grp >> 1) * 16);
    uint32_t bRel[2];
#pragma unroll
    for (int ni2 = 0; ni2 < 2; ni2++)
        bRel[ni2] = (uint32_t)((wn + ni2 * 16 + (grp >> 1) * 8 + rl) * 80
                               + (grp & 1) * 16);

    float acc[4][4][4];
#pragma unroll
    for (int mi = 0; mi < 4; mi++)
#pragma unroll
        for (int ni = 0; ni < 4; ni++)
#pragma unroll
            for (int r = 0; r < 4; r++) acc[mi][ni][r] = 0.f;

    const __nv_bfloat16* srcs[4] = {Ahi, Alo, Bhi, Blo};
    auto load_tile = [&](int kt, int buf) {
        const int k0 = kt * GBK;
#pragma unroll
        for (int t = 0; t < 4; t++) {
            const __nv_bfloat16* base = srcs[t] +
                (size_t)((t < 2) ? row0 : col0) * K + k0;
#pragma unroll
            for (int it = 0; it < 2; it++) {
                int idx = tid + it * 256;
                int r   = idx >> 2;
                int f   = idx & 3;
                cp_async16(&tiles[buf][t][r * TSTRIDE + f * 4],
                           base + (size_t)r * K + f * 8);
            }
        }
        cp_commit();
    };

    load_tile(0, 0);
    cp_wait0();
    __syncthreads();

    const int KT = K / GBK;
    for (int kt = 0; kt < KT; kt++) {
        const int buf = kt & 1;
        if (kt + 1 < KT) load_tile(kt + 1, buf ^ 1);

        const uint32_t baseAh = smem_u32(tiles[buf][0]);
        const uint32_t baseAl = smem_u32(tiles[buf][1]);
        const uint32_t baseBh = smem_u32(tiles[buf][2]);
        const uint32_t baseBl = smem_u32(tiles[buf][3]);

#pragma unroll
        for (int ks = 0; ks < 2; ks++) {
            const uint32_t ko = (uint32_t)ks * 32;
            uint32_t ah[4][4], al[4][4], bh[4][2], bl[4][2];
#pragma unroll
            for (int mi = 0; mi < 4; mi++) {
                ldsm_x4(ah[mi], baseAh + aRel[mi] + ko);
                ldsm_x4(al[mi], baseAl + aRel[mi] + ko);
            }
#pragma unroll
            for (int ni2 = 0; ni2 < 2; ni2++) {
                uint32_t t4[4];
                ldsm_x4(t4, baseBh + bRel[ni2] + ko);
                bh[2*ni2][0] = t4[0]; bh[2*ni2][1] = t4[1];
                bh[2*ni2+1][0] = t4[2]; bh[2*ni2+1][1] = t4[3];
                ldsm_x4(t4, baseBl + bRel[ni2] + ko);
                bl[2*ni2][0] = t4[0]; bl[2*ni2][1] = t4[1];
                bl[2*ni2+1][0] = t4[2]; bl[2*ni2+1][1] = t4[3];
            }
#pragma unroll
            for (int mi = 0; mi < 4; mi++)
#pragma unroll
                for (int ni = 0; ni < 4; ni++) {
                    mma_bf16(acc[mi][ni], ah[mi], bh[ni]);
                    mma_bf16(acc[mi][ni], ah[mi], bl[ni]);
                    mma_bf16(acc[mi][ni], al[mi], bh[ni]);
                }
        }

        if (kt + 1 < KT) cp_wait0();
        __syncthreads();
    }

#pragma unroll
    for (int mi = 0; mi < 4; mi++) {
#pragma unroll
        for (int ni = 0; ni < 4; ni++) {
            int r = row0 + wm + mi * 16 + g;
            int c = col0 + wn + ni * 8 + 2 * q;
            float b0 = bias[c], b1 = bias[c + 1];
            float v00 = acc[mi][ni][0] + b0, v01 = acc[mi][ni][1] + b1;
            float v10 = acc[mi][ni][2] + b0, v11 = acc[mi][ni][3] + b1;
            if (Chi) {
                float r0, r1;
                uint32_t hw0 = pack_hi_pair(v00, v01, r0, r1);
                uint32_t lw0 = pack_bf16x2(r0, r1);
                uint32_t hw1 = pack_hi_pair(v10, v11, r0, r1);
                uint32_t lw1 = pack_bf16x2(r0, r1);
                *(uint32_t*)(Chi + (size_t)r * N + c)       = hw0;
                *(uint32_t*)(Clo + (size_t)r * N + c)       = lw0;
                *(uint32_t*)(Chi + (size_t)(r + 8) * N + c) = hw1;
                *(uint32_t*)(Clo + (size_t)(r + 8) * N + c) = lw1;
            } else {
                *(float2*)(Cout + (size_t)r * N + c)       = make_float2(v00, v01);
                *(float2*)(Cout + (size_t)(r + 8) * N + c) = make_float2(v10, v11);
            }
        }
    }
}

// ================= MMA flash attention (bf16 hi/lo inputs, fp32 softmax) ========
// Block: 256 threads = 8 warps, 128 queries of one (b,h). 64-key tiles,
// double-buffered cp.async. K via ldmatrix, V via ldmatrix.trans.
// SMEM buffer (uint32 words, per buf 9216 = 36 KB): Khi@0 Klo@2304 Vhi@4608 Vlo@6912
// rows: 64 bf16 = 128 B + 16 B pad => 36 words/row (conflict-free ldmatrix).
#define ATT_SMEM (2 * 9216 * 4)

__global__ __launch_bounds__(256) void attn_mma_kernel(
    const __nv_bfloat16* __restrict__ qkvhi,
    const __nv_bfloat16* __restrict__ qkvlo,
    __nv_bfloat16* __restrict__ yhi, __nv_bfloat16* __restrict__ ylo)
{
    extern __shared__ uint32_t smd[];
    uint32_t* smB[2] = {smd, smd + 9216};

    const int tid  = threadIdx.x;
    const int w    = tid >> 5;
    const int lane = tid & 31;
    const int g    = lane >> 2;
    const int q    = lane & 3;
    const int grp  = lane >> 3;
    const int rl   = lane & 7;
    const int bh   = blockIdx.x;
    const int b    = bh >> 4;
    const int h    = bh & 15;
    const int qt   = (gridDim.y - 1) - blockIdx.y;   // heavy blocks first
    const int qb   = qt * 128;

    // ---- stage Q hi/lo into buffer 0, extract fragments, scale by 0.125 ----
#pragma unroll
    for (int it = 0; it < 8; it++) {
        int idx = tid + it * 256;            // 0..2047
        int arr = idx >> 10;                 // 0=hi,1=lo
        int rem = idx & 1023;
        int row = rem >> 3;
        int ch  = rem & 7;
        const __nv_bfloat16* src = (arr ? qkvlo : qkvhi)
            + (size_t)(b * T_ + qb + row) * C3_ + h * HD_ + ch * 8;
        cp_async16(&smB[0][arr * 4608 + row * 36 + ch * 4], src);
    }
    cp_commit();
    cp_wait0();
    __syncthreads();

    uint32_t qh[4][4], ql[4][4];
    {
        uint32_t qa = smem_u32(&smB[0][0])
            + (uint32_t)((w * 16 + (grp & 1) * 8 + rl) * 144 + (grp >> 1) * 16);
#pragma unroll
        for (int ks = 0; ks < 4; ks++) {
            ldsm_x4(qh[ks], qa + ks * 32);
            ldsm_x4(ql[ks], qa + 4608 * 4 + ks * 32);
        }
        const __nv_bfloat162 sc = __float2bfloat162_rn(0.125f);  // exact scale
#pragma unroll
        for (int ks = 0; ks < 4; ks++)
#pragma unroll
            for (int i = 0; i < 4; i++) {
                __nv_bfloat162 t = *(__nv_bfloat162*)&qh[ks][i];
                t = __hmul2(t, sc);
                qh[ks][i] = *(uint32_t*)&t;
                t = *(__nv_bfloat162*)&ql[ks][i];
                t = __hmul2(t, sc);
                ql[ks][i] = *(uint32_t*)&t;
            }
    }
    __syncthreads();   // buffer 0 free for K/V

    // K/V tile sources: [arr] 0=Khi 1=Klo 2=Vhi 3=Vlo
    const __nv_bfloat16* kv_src[4] = {
        qkvhi + C_, qkvlo + C_, qkvhi + 2 * C_, qkvlo + 2 * C_
    };
    auto load_tile = [&](int kt, int bufi) {
        const int k0 = kt * 64;
#pragma unroll
        for (int it = 0; it < 8; it++) {
            int idx = tid + it * 256;        // 0..2047
            int arr = idx >> 9;              // 0..3
            int rem = idx & 511;
            int row = rem >> 3;
            int ch  = rem & 7;
            const __nv_bfloat16* src = kv_src[arr]
                + (size_t)(b * T_ + k0 + row) * C3_ + h * HD_ + ch * 8;
            cp_async16(&smB[bufi][arr * 2304 + row * 36 + ch * 4], src);
        }
        cp_commit();
    };

    float o[8][4];
#pragma unroll
    for (int nj = 0; nj < 8; nj++)
#pragma unroll
        for (int c = 0; c < 4; c++) o[nj][c] = 0.f;
    float m0 = -INFINITY, m1 = -INFINITY;
    float l0 = 0.f, l1 = 0.f;

    const int qrow0 = qb + w * 16 + g;
    const int qrow1 = qrow0 + 8;
    const int qmax_w = qb + w * 16 + 15;
    const int kt_max = (qb + 127) >> 6;

    load_tile(0, 0);
    cp_wait0();
    __syncthreads();

    for (int kt = 0; kt <= kt_max; kt++) {
        const int bufi = kt & 1;
        const int k0 = kt * 64;
        if (kt + 1 <= kt_max) load_tile(kt + 1, bufi ^ 1);

        if (k0 <= qmax_w) {
            const uint32_t sb = smem_u32(&smB[bufi][0]);

            // ---- S = Q K^T (3-term split) ----
            float s[8][4];
#pragma unroll
            for (int ni2 = 0; ni2 < 4; ni2++) {
#pragma unroll
                for (int c = 0; c < 4; c++) {
                    s[2*ni2][c] = 0.f; s[2*ni2+1][c] = 0.f;
                }
                const uint32_t ka = sb
                    + (uint32_t)((ni2 * 16 + (grp >> 1) * 8 + rl) * 144
                                 + (grp & 1) * 16);
#pragma unroll
                for (int ks = 0; ks < 4; ks++) {
                    uint32_t bh4[4], bl4[4];
                    ldsm_x4(bh4, ka + ks * 32);
                    ldsm_x4(bl4, ka + 2304 * 4 + ks * 32);
                    mma_bf16(s[2*ni2],   qh[ks], bh4);
                    mma_bf16(s[2*ni2],   qh[ks], bl4);
                    mma_bf16(s[2*ni2],   ql[ks], bh4);
                    mma_bf16(s[2*ni2+1], qh[ks], bh4 + 2);
                    mma_bf16(s[2*ni2+1], qh[ks], bl4 + 2);
                    mma_bf16(s[2*ni2+1], ql[ks], bh4 + 2);
                }
            }

            // ---- causal mask ----
            if (k0 + 63 > qb + w * 16) {
#pragma unroll
                for (int ni = 0; ni < 8; ni++) {
                    int key = k0 + 8 * ni + 2 * q;
                    s[ni][0] = (key     <= qrow0) ? s[ni][0] : -INFINITY;
                    s[ni][1] = (key + 1 <= qrow0) ? s[ni][1] : -INFINITY;
                    s[ni][2] = (key     <= qrow1) ? s[ni][2] : -INFINITY;
                    s[ni][3] = (key + 1 <= qrow1) ? s[ni][3] : -INFINITY;
                }
            }

            // ---- online softmax ----
            float mx0 = s[0][0], mx1 = s[0][2];
#pragma unroll
            for (int ni = 0; ni < 8; ni++) {
                mx0 = fmaxf(mx0, fmaxf(s[ni][0], s[ni][1]));
                mx1 = fmaxf(mx1, fmaxf(s[ni][2], s[ni][3]));
            }
            mx0 = fmaxf(mx0, __shfl_xor_sync(0xffffffff, mx0, 1));
            mx0 = fmaxf(mx0, __shfl_xor_sync(0xffffffff, mx0, 2));
            mx1 = fmaxf(mx1, __shfl_xor_sync(0xffffffff, mx1, 1));
            mx1 = fmaxf(mx1, __shfl_xor_sync(0xffffffff, mx1, 2));

            float mn0 = fmaxf(m0, mx0), mn1 = fmaxf(m1, mx1);
            float al0 = __expf(m0 - mn0), al1 = __expf(m1 - mn1);
            m0 = mn0; m1 = mn1;
            l0 *= al0; l1 *= al1;
#pragma unroll
            for (int nj = 0; nj < 8; nj++) {
                o[nj][0] *= al0; o[nj][1] *= al0;
                o[nj][2] *= al1; o[nj][3] *= al1;
            }

            // ---- per k16 step: pack P, accumulate O += P V ----
#pragma unroll
            for (int ks = 0; ks < 4; ks++) {
                uint32_t af_hi[4], af_lo[4];
#pragma unroll
                for (int half = 0; half < 2; half++) {
                    const int ni = 2 * ks + half;
                    float p0 = __expf(s[ni][0] - mn0);
                    float p1 = __expf(s[ni][1] - mn0);
                    float p2 = __expf(s[ni][2] - mn1);
                    float p3 = __expf(s[ni][3] - mn1);
                    l0 += p0 + p1;
                    l1 += p2 + p3;
                    float r0, r1, r2, r3;
                    af_hi[2*half]     = pack_hi_pair(p0, p1, r0, r1);
                    af_lo[2*half]     = pack_bf16x2(r0, r1);
                    af_hi[2*half + 1] = pack_hi_pair(p2, p3, r2, r3);
                    af_lo[2*half + 1] = pack_bf16x2(r2, r3);
                }
                const uint32_t va = sb + 4608 * 4
                    + (uint32_t)((ks * 16 + (grp & 1) * 8 + rl) * 144
                                 + (grp >> 1) * 16);
#pragma unroll
                for (int nj2 = 0; nj2 < 4; nj2++) {
                    uint32_t vh4[4], vl4[4];
                    ldsm_x4_trans(vh4, va + nj2 * 32);
                    ldsm_x4_trans(vl4, va + 2304 * 4 + nj2 * 32);
                    mma_bf16(o[2*nj2],   af_hi, vh4);
                    mma_bf16(o[2*nj2],   af_hi, vl4);
                    mma_bf16(o[2*nj2],   af_lo, vh4);
                    mma_bf16(o[2*nj2+1], af_hi, vh4 + 2);
                    mma_bf16(o[2*nj2+1], af_hi, vl4 + 2);
                    mma_bf16(o[2*nj2+1], af_lo, vh4 + 2);
                }
            }
        }

        cp_wait0();
        __syncthreads();
    }

    // ---- epilogue ----
    l0 += __shfl_xor_sync(0xffffffff, l0, 1);
    l0 += __shfl_xor_sync(0xffffffff, l0, 2);
    l1 += __shfl_xor_sync(0xffffffff, l1, 1);
    l1 += __shfl_xor_sync(0xffffffff, l1, 2);
    const float inv0 = 1.f / l0;
    const float inv1 = 1.f / l1;

    __nv_bfloat16* yh0 = yhi + (size_t)(b * T_ + qrow0) * C_ + h * HD_;
    __nv_bfloat16* yl0 = ylo + (size_t)(b * T_ + qrow0) * C_ + h * HD_;
    __nv_bfloat16* yh1 = yhi + (size_t)(b * T_ + qrow1) * C_ + h * HD_;
    __nv_bfloat16* yl1 = ylo + (size_t)(b * T_ + qrow1) * C_ + h * HD_;
#pragma unroll
    for (int nj = 0; nj < 8; nj++) {
        int c = 8 * nj + 2 * q;
        float a0 = o[nj][0] * inv0, a1 = o[nj][1] * inv0;
        float a2 = o[nj][2] * inv1, a3 = o[nj][3] * inv1;
        float r0, r1, r2, r3;
        uint32_t h01 = pack_hi_pair(a0, a1, r0, r1);
        uint32_t h23 = pack_hi_pair(a2, a3, r2, r3);
        *(uint32_t*)(yh0 + c) = h01;
        *(uint32_t*)(yl0 + c) = pack_bf16x2(r0, r1);
        *(uint32_t*)(yh1 + c) = h23;
        *(uint32_t*)(yl1 + c) = pack_bf16x2(r2, r3);
    }
}

// ---------------- launch ----------------
extern "C" void kernel_launch(void* const* d_in, const int* in_sizes, int n_in,
                              void* d_out, int out_size)
{
    const float* x     = (const float*)d_in[0];
    const float* w_qkv = (const float*)d_in[1];
    const float* b_qkv = (const float*)d_in[2];
    const float* w_out = (const float*)d_in[3];
    const float* b_out = (const float*)d_in[4];
    float* out = (float*)d_out;

    __nv_bfloat16 *qkvhi, *qkvlo, *xhi, *xlo, *yhi, *ylo, *wqhi, *wqlo, *wohi, *wolo;
    cudaGetSymbolAddress((void**)&qkvhi, g_qkv_hi);
    cudaGetSymbolAddress((void**)&qkvlo, g_qkv_lo);
    cudaGetSymbolAddress((void**)&xhi, g_x_hi);
    cudaGetSymbolAddress((void**)&xlo, g_x_lo);
    cudaGetSymbolAddress((void**)&yhi, g_y_hi);
    cudaGetSymbolAddress((void**)&ylo, g_y_lo);
    cudaGetSymbolAddress((void**)&wqhi, g_wqkvT_hi);
    cudaGetSymbolAddress((void**)&wqlo, g_wqkvT_lo);
    cudaGetSymbolAddress((void**)&wohi, g_woutT_hi);
    cudaGetSymbolAddress((void**)&wolo, g_woutT_lo);

    static bool attr_set = false;
    if (!attr_set) {
        cudaFuncSetAttribute(gemm_bf16x2_kernel,
                             cudaFuncAttributeMaxDynamicSharedMemorySize,
                             8 * TILE_WORDS * 4);
        cudaFuncSetAttribute(attn_mma_kernel,
                             cudaFuncAttributeMaxDynamicSharedMemorySize,
                             ATT_SMEM);
        attr_set = true;
    }
    const int gemm_smem = 8 * TILE_WORDS * 4;   // 81920 B

    split_f32_kernel<<<1024, 256>>>(x, xhi, xlo, M_ * C_);
    {
        dim3 grid(C3_ / 32, C_ / 32), blk(32, 8);
        split_transpose_kernel<<<grid, blk>>>(w_qkv, wqhi, wqlo, C_, C3_);
    }
    {
        dim3 grid(C_ / 32, C_ / 32), blk(32, 8);
        split_transpose_kernel<<<grid, blk>>>(w_out, wohi, wolo, C_, C_);
    }

    // 1) qkv = x @ w_qkv + b_qkv  -> hi/lo bf16
    {
        dim3 grid(C3_ / GBN, M_ / GBM);
        gemm_bf16x2_kernel<<<grid, 256, gemm_smem>>>(
            xhi, xlo, wqhi, wqlo, b_qkv, nullptr, qkvhi, qkvlo, M_, C3_, C_);
    }

    // 2) causal attention -> y (hi/lo bf16)
    {
        dim3 grid(B_ * H_, T_ / 128);
        attn_mma_kernel<<<grid, 256, ATT_SMEM>>>(qkvhi, qkvlo, yhi, ylo);
    }

    // 3) out = y @ w_out + b_out  -> fp32
    {
        dim3 grid(C_ / GBN, M_ / GBM);
        gemm_bf16x2_kernel<<<grid, 256, gemm_smem>>>(
            yhi, ylo, wohi, wolo, b_out, out, nullptr, nullptr, M_, C_, C_);
    }
}